// round 1
// baseline (speedup 1.0000x reference)
#include <cuda_runtime.h>

#define N_NODES 50000
#define N_EDGES 800000
#define DNODE   128
#define DEDGE   32
#define HID     128

typedef unsigned long long u64;

// ---------------- device-global scratch (no allocations allowed) ----------------
__device__ int   g_src[N_EDGES];
__device__ int   g_dst[N_EDGES];
__device__ float g_mi[(size_t)N_NODES * HID];   // 25.6 MB scatter target
__device__ int   g_is64;

// ---------------- packed f32x2 helpers (Blackwell FFMA2 path) ----------------
__device__ __forceinline__ u64 pk2(float lo, float hi) {
    u64 r;
    asm("mov.b64 %0, {%1, %2};" : "=l"(r) : "f"(lo), "f"(hi));
    return r;
}
__device__ __forceinline__ void fma2(u64& d, u64 a, u64 b) {
    asm("fma.rn.f32x2 %0, %1, %2, %0;" : "+l"(d) : "l"(a), "l"(b));
}
__device__ __forceinline__ float2 upk2(u64 v) {
    float2 f;
    asm("mov.b64 {%0, %1}, %2;" : "=f"(f.x), "=f"(f.y) : "l"(v));
    return f;
}

// ---------------- edge_index dtype sniffing ----------------
// jax code asks for int64; without JAX x64 it is int32. If the buffer is int64,
// every odd 32-bit word is a zero high-word (values in [0, 50000)). If int32,
// odd words are random node ids (P(zero) = 2e-5 each).
__global__ void detect_kernel(const int* __restrict__ ei) {
    if (threadIdx.x == 0) {
        int all0 = 1;
        for (int s = 0; s < 512; s++) {
            if (ei[2 * s + 1] != 0) { all0 = 0; break; }
        }
        g_is64 = all0;
    }
}

__global__ void convert_kernel(const void* __restrict__ ei) {
    int i = blockIdx.x * blockDim.x + threadIdx.x;
    if (i >= N_EDGES) return;
    if (g_is64) {
        const long long* p = (const long long*)ei;
        g_src[i] = (int)p[i];
        g_dst[i] = (int)p[N_EDGES + i];
    } else {
        const int* p = (const int*)ei;
        g_src[i] = p[i];
        g_dst[i] = p[N_EDGES + i];
    }
}

__global__ void zero_kernel() {
    size_t n = (size_t)N_NODES * HID;
    for (size_t i = (size_t)blockIdx.x * blockDim.x + threadIdx.x; i < n;
         i += (size_t)gridDim.x * blockDim.x)
        g_mi[i] = 0.0f;
}

// =================================================================
// Edge MLP kernel: per block, 64 edges.
//   layer1: X[64,288] @ W1[288,128] + b1, relu   (X gathered: h[src]|h[dst]|ea)
//   layer2: Y[64,128] @ W2[128,128] + b2
//   scatter: atomicAdd into g_mi[dst]
// Thread map: 256 threads = 16(tx: col groups of 8) x 16(ty: edge groups of 4).
// Accumulators: 4 edges x 8 cols as 4x4 packed f32x2.
// =================================================================
__global__ __launch_bounds__(256) void edge_kernel(
    const float* __restrict__ h,  const float* __restrict__ ea,
    const float* __restrict__ W1, const float* __restrict__ b1,
    const float* __restrict__ W2, const float* __restrict__ b2)
{
    __shared__ float Xs[64][17];    // K-chunk of X, padded (bank-conflict free reads)
    __shared__ float Ws[16][128];   // K-chunk of W
    __shared__ float Ys[64][129];   // full hidden activations, padded
    __shared__ int   sSrc[64], sDst[64];

    const int t  = threadIdx.x;
    const int e0 = blockIdx.x * 64;
    if (t < 64) { sSrc[t] = g_src[e0 + t]; sDst[t] = g_dst[e0 + t]; }

    const int tx = t & 15, ty = t >> 4;
    const int eb = ty * 4, cb = tx * 8;

    u64 acc[4][4];
#pragma unroll
    for (int j = 0; j < 4; j++) {
        u64 bj = pk2(b1[cb + 2 * j], b1[cb + 2 * j + 1]);
        acc[0][j] = bj; acc[1][j] = bj; acc[2][j] = bj; acc[3][j] = bj;
    }
    __syncthreads();

    const int le = t >> 2, lj = t & 3;   // Xs loader: edge le, float4 slot lj

    // ---- layer 1: K = 288 = 18 chunks of 16 ----
    for (int ch = 0; ch < 18; ch++) {
        const float* p;
        if (ch < 8)       p = h  + (size_t)sSrc[le] * DNODE + ch * 16;
        else if (ch < 16) p = h  + (size_t)sDst[le] * DNODE + (ch - 8) * 16;
        else              p = ea + (size_t)(e0 + le) * DEDGE + (ch - 16) * 16;
        float4 v = *(const float4*)(p + lj * 4);

        const float* wsrc = W1 + (size_t)ch * 16 * 128;
#pragma unroll
        for (int r2 = 0; r2 < 2; r2++) {
            int f = t + r2 * 256;
            int row = f >> 5, c = (f & 31) * 4;
            *(float4*)&Ws[row][c] = *(const float4*)(wsrc + row * 128 + c);
        }
        Xs[le][lj * 4 + 0] = v.x; Xs[le][lj * 4 + 1] = v.y;
        Xs[le][lj * 4 + 2] = v.z; Xs[le][lj * 4 + 3] = v.w;
        __syncthreads();

#pragma unroll
        for (int kk = 0; kk < 16; kk++) {
            ulonglong2 w01 = *(const ulonglong2*)&Ws[kk][cb];
            ulonglong2 w23 = *(const ulonglong2*)&Ws[kk][cb + 4];
            float a0 = Xs[eb + 0][kk], a1 = Xs[eb + 1][kk];
            float a2 = Xs[eb + 2][kk], a3 = Xs[eb + 3][kk];
            u64 A0 = pk2(a0, a0), A1 = pk2(a1, a1), A2 = pk2(a2, a2), A3 = pk2(a3, a3);
            fma2(acc[0][0], A0, w01.x); fma2(acc[0][1], A0, w01.y);
            fma2(acc[0][2], A0, w23.x); fma2(acc[0][3], A0, w23.y);
            fma2(acc[1][0], A1, w01.x); fma2(acc[1][1], A1, w01.y);
            fma2(acc[1][2], A1, w23.x); fma2(acc[1][3], A1, w23.y);
            fma2(acc[2][0], A2, w01.x); fma2(acc[2][1], A2, w01.y);
            fma2(acc[2][2], A2, w23.x); fma2(acc[2][3], A2, w23.y);
            fma2(acc[3][0], A3, w01.x); fma2(acc[3][1], A3, w01.y);
            fma2(acc[3][2], A3, w23.x); fma2(acc[3][3], A3, w23.y);
        }
        __syncthreads();
    }

    // ---- relu + stage Y, re-init acc with b2 ----
#pragma unroll
    for (int i = 0; i < 4; i++)
#pragma unroll
        for (int j = 0; j < 4; j++) {
            float2 v = upk2(acc[i][j]);
            Ys[eb + i][cb + 2 * j]     = fmaxf(v.x, 0.0f);
            Ys[eb + i][cb + 2 * j + 1] = fmaxf(v.y, 0.0f);
        }
#pragma unroll
    for (int j = 0; j < 4; j++) {
        u64 bj = pk2(b2[cb + 2 * j], b2[cb + 2 * j + 1]);
        acc[0][j] = bj; acc[1][j] = bj; acc[2][j] = bj; acc[3][j] = bj;
    }
    __syncthreads();

    // ---- layer 2: K = 128 = 8 chunks of 16, A read from Ys ----
    for (int ch = 0; ch < 8; ch++) {
        const float* wsrc = W2 + (size_t)ch * 16 * 128;
#pragma unroll
        for (int r2 = 0; r2 < 2; r2++) {
            int f = t + r2 * 256;
            int row = f >> 5, c = (f & 31) * 4;
            *(float4*)&Ws[row][c] = *(const float4*)(wsrc + row * 128 + c);
        }
        __syncthreads();
#pragma unroll
        for (int kk = 0; kk < 16; kk++) {
            int k = ch * 16 + kk;
            ulonglong2 w01 = *(const ulonglong2*)&Ws[kk][cb];
            ulonglong2 w23 = *(const ulonglong2*)&Ws[kk][cb + 4];
            float a0 = Ys[eb + 0][k], a1 = Ys[eb + 1][k];
            float a2 = Ys[eb + 2][k], a3 = Ys[eb + 3][k];
            u64 A0 = pk2(a0, a0), A1 = pk2(a1, a1), A2 = pk2(a2, a2), A3 = pk2(a3, a3);
            fma2(acc[0][0], A0, w01.x); fma2(acc[0][1], A0, w01.y);
            fma2(acc[0][2], A0, w23.x); fma2(acc[0][3], A0, w23.y);
            fma2(acc[1][0], A1, w01.x); fma2(acc[1][1], A1, w01.y);
            fma2(acc[1][2], A1, w23.x); fma2(acc[1][3], A1, w23.y);
            fma2(acc[2][0], A2, w01.x); fma2(acc[2][1], A2, w01.y);
            fma2(acc[2][2], A2, w23.x); fma2(acc[2][3], A2, w23.y);
            fma2(acc[3][0], A3, w01.x); fma2(acc[3][1], A3, w01.y);
            fma2(acc[3][2], A3, w23.x); fma2(acc[3][3], A3, w23.y);
        }
        __syncthreads();
    }

    // ---- scatter-add messages into g_mi[dst] ----
#pragma unroll
    for (int i = 0; i < 4; i++) {
        float* dp = g_mi + (size_t)sDst[eb + i] * HID + cb;
#pragma unroll
        for (int j = 0; j < 4; j++) {
            float2 v = upk2(acc[i][j]);
            atomicAdd(dp + 2 * j,     v.x);
            atomicAdd(dp + 2 * j + 1, v.y);
        }
    }
}

// =================================================================
// Node MLP kernel: per block, 64 nodes.
//   X = [h[i] | m_i[i]]  (K = 256), layer1 -> relu -> layer2 -> out
// =================================================================
__global__ __launch_bounds__(256) void node_kernel(
    const float* __restrict__ h,
    const float* __restrict__ W1, const float* __restrict__ b1,
    const float* __restrict__ W2, const float* __restrict__ b2,
    float* __restrict__ out)
{
    __shared__ float Xs[64][17];
    __shared__ float Ws[16][128];
    __shared__ float Ys[64][129];

    const int t  = threadIdx.x;
    const int r0 = blockIdx.x * 64;
    const int tx = t & 15, ty = t >> 4;
    const int eb = ty * 4, cb = tx * 8;

    u64 acc[4][4];
#pragma unroll
    for (int j = 0; j < 4; j++) {
        u64 bj = pk2(b1[cb + 2 * j], b1[cb + 2 * j + 1]);
        acc[0][j] = bj; acc[1][j] = bj; acc[2][j] = bj; acc[3][j] = bj;
    }

    const int le = t >> 2, lj = t & 3;
    const int lr = (r0 + le < N_NODES) ? (r0 + le) : 0;   // clamp OOB gathers

    // ---- layer 1: K = 256 = 16 chunks of 16 ----
    for (int ch = 0; ch < 16; ch++) {
        const float* p;
        if (ch < 8) p = h    + (size_t)lr * DNODE + ch * 16;
        else        p = g_mi + (size_t)lr * HID   + (ch - 8) * 16;
        float4 v = *(const float4*)(p + lj * 4);

        const float* wsrc = W1 + (size_t)ch * 16 * 128;
#pragma unroll
        for (int r2 = 0; r2 < 2; r2++) {
            int f = t + r2 * 256;
            int row = f >> 5, c = (f & 31) * 4;
            *(float4*)&Ws[row][c] = *(const float4*)(wsrc + row * 128 + c);
        }
        Xs[le][lj * 4 + 0] = v.x; Xs[le][lj * 4 + 1] = v.y;
        Xs[le][lj * 4 + 2] = v.z; Xs[le][lj * 4 + 3] = v.w;
        __syncthreads();

#pragma unroll
        for (int kk = 0; kk < 16; kk++) {
            ulonglong2 w01 = *(const ulonglong2*)&Ws[kk][cb];
            ulonglong2 w23 = *(const ulonglong2*)&Ws[kk][cb + 4];
            float a0 = Xs[eb + 0][kk], a1 = Xs[eb + 1][kk];
            float a2 = Xs[eb + 2][kk], a3 = Xs[eb + 3][kk];
            u64 A0 = pk2(a0, a0), A1 = pk2(a1, a1), A2 = pk2(a2, a2), A3 = pk2(a3, a3);
            fma2(acc[0][0], A0, w01.x); fma2(acc[0][1], A0, w01.y);
            fma2(acc[0][2], A0, w23.x); fma2(acc[0][3], A0, w23.y);
            fma2(acc[1][0], A1, w01.x); fma2(acc[1][1], A1, w01.y);
            fma2(acc[1][2], A1, w23.x); fma2(acc[1][3], A1, w23.y);
            fma2(acc[2][0], A2, w01.x); fma2(acc[2][1], A2, w01.y);
            fma2(acc[2][2], A2, w23.x); fma2(acc[2][3], A2, w23.y);
            fma2(acc[3][0], A3, w01.x); fma2(acc[3][1], A3, w01.y);
            fma2(acc[3][2], A3, w23.x); fma2(acc[3][3], A3, w23.y);
        }
        __syncthreads();
    }

#pragma unroll
    for (int i = 0; i < 4; i++)
#pragma unroll
        for (int j = 0; j < 4; j++) {
            float2 v = upk2(acc[i][j]);
            Ys[eb + i][cb + 2 * j]     = fmaxf(v.x, 0.0f);
            Ys[eb + i][cb + 2 * j + 1] = fmaxf(v.y, 0.0f);
        }
#pragma unroll
    for (int j = 0; j < 4; j++) {
        u64 bj = pk2(b2[cb + 2 * j], b2[cb + 2 * j + 1]);
        acc[0][j] = bj; acc[1][j] = bj; acc[2][j] = bj; acc[3][j] = bj;
    }
    __syncthreads();

    // ---- layer 2: K = 128 = 8 chunks of 16 ----
    for (int ch = 0; ch < 8; ch++) {
        const float* wsrc = W2 + (size_t)ch * 16 * 128;
#pragma unroll
        for (int r2 = 0; r2 < 2; r2++) {
            int f = t + r2 * 256;
            int row = f >> 5, c = (f & 31) * 4;
            *(float4*)&Ws[row][c] = *(const float4*)(wsrc + row * 128 + c);
        }
        __syncthreads();
#pragma unroll
        for (int kk = 0; kk < 16; kk++) {
            int k = ch * 16 + kk;
            ulonglong2 w01 = *(const ulonglong2*)&Ws[kk][cb];
            ulonglong2 w23 = *(const ulonglong2*)&Ws[kk][cb + 4];
            float a0 = Ys[eb + 0][k], a1 = Ys[eb + 1][k];
            float a2 = Ys[eb + 2][k], a3 = Ys[eb + 3][k];
            u64 A0 = pk2(a0, a0), A1 = pk2(a1, a1), A2 = pk2(a2, a2), A3 = pk2(a3, a3);
            fma2(acc[0][0], A0, w01.x); fma2(acc[0][1], A0, w01.y);
            fma2(acc[0][2], A0, w23.x); fma2(acc[0][3], A0, w23.y);
            fma2(acc[1][0], A1, w01.x); fma2(acc[1][1], A1, w01.y);
            fma2(acc[1][2], A1, w23.x); fma2(acc[1][3], A1, w23.y);
            fma2(acc[2][0], A2, w01.x); fma2(acc[2][1], A2, w01.y);
            fma2(acc[2][2], A2, w23.x); fma2(acc[2][3], A2, w23.y);
            fma2(acc[3][0], A3, w01.x); fma2(acc[3][1], A3, w01.y);
            fma2(acc[3][2], A3, w23.x); fma2(acc[3][3], A3, w23.y);
        }
        __syncthreads();
    }

    // ---- store output ----
#pragma unroll
    for (int i = 0; i < 4; i++) {
        int row = r0 + eb + i;
        if (row < N_NODES) {
            float* op = out + (size_t)row * 128 + cb;
#pragma unroll
            for (int j = 0; j < 4; j++) {
                float2 v = upk2(acc[i][j]);
                op[2 * j]     = v.x;
                op[2 * j + 1] = v.y;
            }
        }
    }
}

// =================================================================
extern "C" void kernel_launch(void* const* d_in, const int* in_sizes, int n_in,
                              void* d_out, int out_size) {
    const float* h   = (const float*)d_in[0];
    const void*  ei  = d_in[1];
    const float* ea  = (const float*)d_in[2];
    const float* We1 = (const float*)d_in[3];
    const float* be1 = (const float*)d_in[4];
    const float* We2 = (const float*)d_in[5];
    const float* be2 = (const float*)d_in[6];
    const float* Wh1 = (const float*)d_in[7];
    const float* bh1 = (const float*)d_in[8];
    const float* Wh2 = (const float*)d_in[9];
    const float* bh2 = (const float*)d_in[10];
    float* out = (float*)d_out;

    detect_kernel<<<1, 32>>>((const int*)ei);
    convert_kernel<<<(N_EDGES + 255) / 256, 256>>>(ei);
    zero_kernel<<<2048, 256>>>();
    edge_kernel<<<N_EDGES / 64, 256>>>(h, ea, We1, be1, We2, be2);
    node_kernel<<<(N_NODES + 63) / 64, 256>>>(h, Wh1, bh1, Wh2, bh2, out);
}

// round 3
// speedup vs baseline: 4.2673x; 4.2673x over previous
#include <cuda_runtime.h>
#include <cstdint>

#define N_NODES 50000
#define N_EDGES 800000
#define DNODE   128
#define DEDGE   32
#define HID     128

typedef unsigned long long u64;

// ---------------- device-global scratch (no allocations allowed) ----------------
__device__ int   g_src[N_EDGES];
__device__ int   g_dst[N_EDGES];
__device__ float g_mi[(size_t)N_NODES * HID];   // 25.6 MB scatter target
__device__ float g_W1r[288 * 128];              // We1, tf32-rounded, [K][N]
__device__ float g_W2r[128 * 128];              // We2, tf32-rounded, [K][N]
__device__ int   g_is64;

// ---------------- helpers ----------------
__device__ __forceinline__ uint32_t smem_u32(const void* p) {
    uint32_t a;
    asm("{ .reg .u64 t; cvta.to.shared.u64 t, %1; cvt.u32.u64 %0, t; }" : "=r"(a) : "l"(p));
    return a;
}
__device__ __forceinline__ uint32_t rna(float x) {
    uint32_t r; asm("cvt.rna.tf32.f32 %0, %1;" : "=r"(r) : "f"(x)); return r;
}
__device__ __forceinline__ u64 pk2(float lo, float hi) {
    u64 r; asm("mov.b64 %0, {%1, %2};" : "=l"(r) : "f"(lo), "f"(hi)); return r;
}
__device__ __forceinline__ void fma2(u64& d, u64 a, u64 b) {
    asm("fma.rn.f32x2 %0, %1, %2, %0;" : "+l"(d) : "l"(a), "l"(b));
}
__device__ __forceinline__ float2 upk2(u64 v) {
    float2 f; asm("mov.b64 {%0, %1}, %2;" : "=f"(f.x), "=f"(f.y) : "l"(v)); return f;
}

#define CP_ASYNC(ds, gp) \
    asm volatile("cp.async.cg.shared.global [%0], [%1], 16;" :: "r"(ds), "l"(gp))
#define CP_COMMIT() asm volatile("cp.async.commit_group;" ::: "memory")
#define CP_WAIT1()  asm volatile("cp.async.wait_group 1;" ::: "memory")
#define CP_WAIT0()  asm volatile("cp.async.wait_group 0;" ::: "memory")

#define MMA_TF32(C, a0, a1, a2, a3, b0, b1) \
    asm volatile("mma.sync.aligned.m16n8k8.row.col.f32.tf32.tf32.f32 " \
        "{%0,%1,%2,%3}, {%4,%5,%6,%7}, {%8,%9}, {%0,%1,%2,%3};" \
        : "+f"((C)[0]), "+f"((C)[1]), "+f"((C)[2]), "+f"((C)[3]) \
        : "r"(a0), "r"(a1), "r"(a2), "r"(a3), "r"(b0), "r"(b1))

// ---------------- aux kernels ----------------
__global__ void detect_kernel(const int* __restrict__ ei) {
    if (threadIdx.x == 0) {
        int all0 = 1;
        for (int s = 0; s < 512; s++)
            if (ei[2 * s + 1] != 0) { all0 = 0; break; }
        g_is64 = all0;
    }
}

__global__ void convert_kernel(const void* __restrict__ ei) {
    int i = blockIdx.x * blockDim.x + threadIdx.x;
    if (i >= N_EDGES) return;
    if (g_is64) {
        const long long* p = (const long long*)ei;
        g_src[i] = (int)p[i];
        g_dst[i] = (int)p[N_EDGES + i];
    } else {
        const int* p = (const int*)ei;
        g_src[i] = p[i];
        g_dst[i] = p[N_EDGES + i];
    }
}

__global__ void zero_kernel() {
    size_t n = (size_t)N_NODES * HID;
    for (size_t i = (size_t)blockIdx.x * blockDim.x + threadIdx.x; i < n;
         i += (size_t)gridDim.x * blockDim.x)
        g_mi[i] = 0.0f;
}

__global__ void prep_kernel(const float* __restrict__ W1, const float* __restrict__ W2) {
    int t = blockIdx.x * blockDim.x + threadIdx.x;
    int stride = gridDim.x * blockDim.x;
    for (int i = t; i < 288 * 128; i += stride)
        g_W1r[i] = __uint_as_float(rna(W1[i]));
    for (int i = t; i < 128 * 128; i += stride)
        g_W2r[i] = __uint_as_float(rna(W2[i]));
}

// =================================================================
// Edge MLP via mma.sync tf32 m16n8k8.
// Block = 256 threads (8 warps), 256 edges. Warp tile 64x64.
// smem map (bytes):
//   [0, 131072)       Ys: 256 rows x 128 words (phase1 X double-buffers overlay:
//                       Xb0 @ 0, Xb1 @ 32768; each 256 rows x 32 words)
//   [131072, 147456)  Wbuf0 (32 k x 128 n words)
//   [147456, 163840)  Wbuf1
//   [163840, 164352)  sb1   [164352, 164864) sb2
//   [164864, 165888)  sSrc  [165888, 166912) sDst
// Swizzles (word granularity):
//   X/Y: word(r,c) = r*RS + (c&~31) + ((c&31) ^ (4*(r&7)))
//   W:   word(k,n) = k*128 + (n ^ (8*(k&3)))
// =================================================================
#define EDGE_SMEM 166912

__global__ __launch_bounds__(256, 1) void edge_kernel_m(
    const float* __restrict__ h, const float* __restrict__ ea,
    const float* __restrict__ b1g, const float* __restrict__ b2g)
{
    extern __shared__ char sm[];
    const uint32_t smb = smem_u32(sm);
    float* Ys  = (float*)sm;
    float* sb1 = (float*)(sm + 163840);
    float* sb2 = (float*)(sm + 164352);
    int*   sSrc = (int*)(sm + 164864);
    int*   sDst = (int*)(sm + 165888);

    const int tid  = threadIdx.x;
    const int lane = tid & 31, wid = tid >> 5;
    const int g    = lane >> 2, t4 = lane & 3;
    const int m0   = (wid >> 1) * 64;     // warp M offset (edges)
    const int n0   = (wid & 1) * 64;      // warp N offset (cols)
    const int e0   = blockIdx.x * 256;

    if (tid < 128) { sb1[tid] = b1g[tid]; sb2[tid] = b2g[tid]; }
    sSrc[tid] = g_src[e0 + tid];
    sDst[tid] = g_dst[e0 + tid];
    __syncthreads();

    // ---- cp.async issue helpers ----
    auto issue_x = [&](int ch, int xb) {
        uint32_t xbase = smb + xb * 32768;
#pragma unroll
        for (int i = 0; i < 8; i++) {
            int f = tid + i * 256;
            int row = f >> 3, q = f & 7;
            const float* gp;
            if (ch < 4)      gp = h + (size_t)sSrc[row] * DNODE + ch * 32 + q * 4;
            else if (ch < 8) gp = h + (size_t)sDst[row] * DNODE + (ch - 4) * 32 + q * 4;
            else             gp = ea + (size_t)(e0 + row) * DEDGE + q * 4;
            uint32_t ds = xbase + 4u * (uint32_t)(row * 32 + ((4 * q) ^ (4 * (row & 7))));
            CP_ASYNC(ds, gp);
        }
    };
    auto issue_w = [&](const float* W, int ch, int wb) {
        uint32_t wbase = smb + 131072 + wb * 16384;
#pragma unroll
        for (int i = 0; i < 4; i++) {
            int f = tid + i * 256;
            int k = f >> 5, n4 = f & 31;
            const float* gp = W + (size_t)(ch * 32 + k) * 128 + n4 * 4;
            uint32_t ds = wbase + 4u * (uint32_t)(k * 128 + ((4 * n4) ^ (8 * (k & 3))));
            CP_ASYNC(ds, gp);
        }
    };

    float c[4][8][4];
#pragma unroll
    for (int mf = 0; mf < 4; mf++)
#pragma unroll
        for (int nf = 0; nf < 8; nf++)
#pragma unroll
            for (int j = 0; j < 4; j++) c[mf][nf][j] = 0.0f;

    // ---- compute one K=32 chunk ----
    auto compute = [&](const uint32_t* Xw, int rstride, int cofs, const uint32_t* Ww) {
#pragma unroll
        for (int s = 0; s < 4; s++) {
            const int kb = 8 * s + t4;
            uint32_t b0r[8], b1r[8];
#pragma unroll
            for (int nf = 0; nf < 8; nf++) {
                int wc = (n0 + 8 * nf + g) ^ (8 * t4);
                b0r[nf] = Ww[kb * 128 + wc];
                b1r[nf] = Ww[(kb + 4) * 128 + wc];
            }
#pragma unroll
            for (int mf = 0; mf < 4; mf++) {
                int base = (m0 + mf * 16 + g) * rstride + cofs;
                uint32_t a0 = Xw[base + (kb ^ (4 * g))];
                uint32_t a1 = Xw[base + 8 * rstride + (kb ^ (4 * g))];
                uint32_t a2 = Xw[base + ((kb + 4) ^ (4 * g))];
                uint32_t a3 = Xw[base + 8 * rstride + ((kb + 4) ^ (4 * g))];
#pragma unroll
                for (int nf = 0; nf < 8; nf++)
                    MMA_TF32(c[mf][nf], a0, a1, a2, a3, b0r[nf], b1r[nf]);
            }
        }
    };

    // ======== phase 1: layer 1, K = 288 = 9 chunks of 32 ========
    issue_x(0, 0); issue_w(g_W1r, 0, 0); CP_COMMIT();
    for (int ch = 0; ch < 9; ch++) {
        if (ch < 8) {
            issue_x(ch + 1, (ch + 1) & 1);
            issue_w(g_W1r, ch + 1, (ch + 1) & 1);
            CP_COMMIT();
            CP_WAIT1();
        } else {
            CP_WAIT0();
        }
        __syncthreads();
        compute((const uint32_t*)(sm) + (ch & 1) * 8192, 32, 0,
                (const uint32_t*)(sm + 131072) + (ch & 1) * 4096);
        __syncthreads();
    }

    // prefetch W2 chunk 0 early, overlap with epilogue
    issue_w(g_W2r, 0, 0); CP_COMMIT();

    // ---- epilogue 1: bias + relu -> Ys (full K=128, swizzled), zero c ----
#pragma unroll
    for (int mf = 0; mf < 4; mf++) {
        int r0 = m0 + mf * 16 + g;
#pragma unroll
        for (int nf = 0; nf < 8; nf++) {
            int cc = n0 + 8 * nf + 2 * t4;
            float bb0 = sb1[cc], bb1 = sb1[cc + 1];
            int w = (cc & ~31) + ((cc & 31) ^ (4 * g));
            float2 v0 = make_float2(fmaxf(c[mf][nf][0] + bb0, 0.0f),
                                    fmaxf(c[mf][nf][1] + bb1, 0.0f));
            float2 v1 = make_float2(fmaxf(c[mf][nf][2] + bb0, 0.0f),
                                    fmaxf(c[mf][nf][3] + bb1, 0.0f));
            *(float2*)&Ys[r0 * 128 + w]       = v0;
            *(float2*)&Ys[(r0 + 8) * 128 + w] = v1;
#pragma unroll
            for (int j = 0; j < 4; j++) c[mf][nf][j] = 0.0f;
        }
    }
    __syncthreads();

    // ======== phase 2: layer 2, K = 128 = 4 chunks of 32 (A from Ys) ========
    for (int ch = 0; ch < 4; ch++) {
        if (ch < 3) {
            issue_w(g_W2r, ch + 1, (ch + 1) & 1);
            CP_COMMIT();
            CP_WAIT1();
        } else {
            CP_WAIT0();
        }
        __syncthreads();
        compute((const uint32_t*)sm, 128, ch * 32,
                (const uint32_t*)(sm + 131072) + (ch & 1) * 4096);
        __syncthreads();
    }

    // ---- stage messages (+bias b2) into Ys ----
#pragma unroll
    for (int mf = 0; mf < 4; mf++) {
        int r0 = m0 + mf * 16 + g;
#pragma unroll
        for (int nf = 0; nf < 8; nf++) {
            int cc = n0 + 8 * nf + 2 * t4;
            float bb0 = sb2[cc], bb1 = sb2[cc + 1];
            int w = (cc & ~31) + ((cc & 31) ^ (4 * g));
            *(float2*)&Ys[r0 * 128 + w] =
                make_float2(c[mf][nf][0] + bb0, c[mf][nf][1] + bb1);
            *(float2*)&Ys[(r0 + 8) * 128 + w] =
                make_float2(c[mf][nf][2] + bb0, c[mf][nf][3] + bb1);
        }
    }
    __syncthreads();

    // ---- coalesced vectorized scatter-add ----
#pragma unroll 4
    for (int i = 0; i < 32; i++) {
        int f = tid + i * 256;
        int row = f >> 5, c4 = f & 31;
        int w = row * 128 + (c4 >> 3) * 32 + ((4 * (c4 & 7)) ^ (4 * (row & 7)));
        float4 v = *(const float4*)&Ys[w];
        float* gp = g_mi + (size_t)sDst[row] * HID + 4 * c4;
        asm volatile("red.global.add.v4.f32 [%0], {%1,%2,%3,%4};"
                     :: "l"(gp), "f"(v.x), "f"(v.y), "f"(v.z), "f"(v.w) : "memory");
    }
}

// =================================================================
// Node MLP kernel (fp32 FFMA2, unchanged — exact math on m_i)
// =================================================================
__global__ __launch_bounds__(256) void node_kernel(
    const float* __restrict__ h,
    const float* __restrict__ W1, const float* __restrict__ b1,
    const float* __restrict__ W2, const float* __restrict__ b2,
    float* __restrict__ out)
{
    __shared__ float Xs[64][17];
    __shared__ float Ws[16][128];
    __shared__ float Ys2[64][129];

    const int t  = threadIdx.x;
    const int r0 = blockIdx.x * 64;
    const int tx = t & 15, ty = t >> 4;
    const int eb = ty * 4, cb = tx * 8;

    u64 acc[4][4];
#pragma unroll
    for (int j = 0; j < 4; j++) {
        u64 bj = pk2(b1[cb + 2 * j], b1[cb + 2 * j + 1]);
        acc[0][j] = bj; acc[1][j] = bj; acc[2][j] = bj; acc[3][j] = bj;
    }

    const int le = t >> 2, lj = t & 3;
    const int lr = (r0 + le < N_NODES) ? (r0 + le) : 0;

    for (int ch = 0; ch < 16; ch++) {
        const float* p;
        if (ch < 8) p = h    + (size_t)lr * DNODE + ch * 16;
        else        p = g_mi + (size_t)lr * HID   + (ch - 8) * 16;
        float4 v = *(const float4*)(p + lj * 4);

        const float* wsrc = W1 + (size_t)ch * 16 * 128;
#pragma unroll
        for (int r2 = 0; r2 < 2; r2++) {
            int f = t + r2 * 256;
            int rw = f >> 5, c = (f & 31) * 4;
            *(float4*)&Ws[rw][c] = *(const float4*)(wsrc + rw * 128 + c);
        }
        Xs[le][lj * 4 + 0] = v.x; Xs[le][lj * 4 + 1] = v.y;
        Xs[le][lj * 4 + 2] = v.z; Xs[le][lj * 4 + 3] = v.w;
        __syncthreads();

#pragma unroll
        for (int kk = 0; kk < 16; kk++) {
            ulonglong2 w01 = *(const ulonglong2*)&Ws[kk][cb];
            ulonglong2 w23 = *(const ulonglong2*)&Ws[kk][cb + 4];
            float a0 = Xs[eb + 0][kk], a1 = Xs[eb + 1][kk];
            float a2 = Xs[eb + 2][kk], a3 = Xs[eb + 3][kk];
            u64 A0 = pk2(a0, a0), A1 = pk2(a1, a1), A2 = pk2(a2, a2), A3 = pk2(a3, a3);
            fma2(acc[0][0], A0, w01.x); fma2(acc[0][1], A0, w01.y);
            fma2(acc[0][2], A0, w23.x); fma2(acc[0][3], A0, w23.y);
            fma2(acc[1][0], A1, w01.x); fma2(acc[1][1], A1, w01.y);
            fma2(acc[1][2], A1, w23.x); fma2(acc[1][3], A1, w23.y);
            fma2(acc[2][0], A2, w01.x); fma2(acc[2][1], A2, w01.y);
            fma2(acc[2][2], A2, w23.x); fma2(acc[2][3], A2, w23.y);
            fma2(acc[3][0], A3, w01.x); fma2(acc[3][1], A3, w01.y);
            fma2(acc[3][2], A3, w23.x); fma2(acc[3][3], A3, w23.y);
        }
        __syncthreads();
    }

#pragma unroll
    for (int i = 0; i < 4; i++)
#pragma unroll
        for (int j = 0; j < 4; j++) {
            float2 v = upk2(acc[i][j]);
            Ys2[eb + i][cb + 2 * j]     = fmaxf(v.x, 0.0f);
            Ys2[eb + i][cb + 2 * j + 1] = fmaxf(v.y, 0.0f);
        }
#pragma unroll
    for (int j = 0; j < 4; j++) {
        u64 bj = pk2(b2[cb + 2 * j], b2[cb + 2 * j + 1]);
        acc[0][j] = bj; acc[1][j] = bj; acc[2][j] = bj; acc[3][j] = bj;
    }
    __syncthreads();

    for (int ch = 0; ch < 8; ch++) {
        const float* wsrc = W2 + (size_t)ch * 16 * 128;
#pragma unroll
        for (int r2 = 0; r2 < 2; r2++) {
            int f = t + r2 * 256;
            int rw = f >> 5, c = (f & 31) * 4;
            *(float4*)&Ws[rw][c] = *(const float4*)(wsrc + rw * 128 + c);
        }
        __syncthreads();
#pragma unroll
        for (int kk = 0; kk < 16; kk++) {
            int k = ch * 16 + kk;
            ulonglong2 w01 = *(const ulonglong2*)&Ws[kk][cb];
            ulonglong2 w23 = *(const ulonglong2*)&Ws[kk][cb + 4];
            float a0 = Ys2[eb + 0][k], a1 = Ys2[eb + 1][k];
            float a2 = Ys2[eb + 2][k], a3 = Ys2[eb + 3][k];
            u64 A0 = pk2(a0, a0), A1 = pk2(a1, a1), A2 = pk2(a2, a2), A3 = pk2(a3, a3);
            fma2(acc[0][0], A0, w01.x); fma2(acc[0][1], A0, w01.y);
            fma2(acc[0][2], A0, w23.x); fma2(acc[0][3], A0, w23.y);
            fma2(acc[1][0], A1, w01.x); fma2(acc[1][1], A1, w01.y);
            fma2(acc[1][2], A1, w23.x); fma2(acc[1][3], A1, w23.y);
            fma2(acc[2][0], A2, w01.x); fma2(acc[2][1], A2, w01.y);
            fma2(acc[2][2], A2, w23.x); fma2(acc[2][3], A2, w23.y);
            fma2(acc[3][0], A3, w01.x); fma2(acc[3][1], A3, w01.y);
            fma2(acc[3][2], A3, w23.x); fma2(acc[3][3], A3, w23.y);
        }
        __syncthreads();
    }

#pragma unroll
    for (int i = 0; i < 4; i++) {
        int rw = r0 + eb + i;
        if (rw < N_NODES) {
            float* op = out + (size_t)rw * 128 + cb;
#pragma unroll
            for (int j = 0; j < 4; j++) {
                float2 v = upk2(acc[i][j]);
                op[2 * j]     = v.x;
                op[2 * j + 1] = v.y;
            }
        }
    }
}

// =================================================================
extern "C" void kernel_launch(void* const* d_in, const int* in_sizes, int n_in,
                              void* d_out, int out_size) {
    const float* h   = (const float*)d_in[0];
    const void*  ei  = d_in[1];
    const float* ea  = (const float*)d_in[2];
    const float* We1 = (const float*)d_in[3];
    const float* be1 = (const float*)d_in[4];
    const float* We2 = (const float*)d_in[5];
    const float* be2 = (const float*)d_in[6];
    const float* Wh1 = (const float*)d_in[7];
    const float* bh1 = (const float*)d_in[8];
    const float* Wh2 = (const float*)d_in[9];
    const float* bh2 = (const float*)d_in[10];
    float* out = (float*)d_out;

    cudaFuncSetAttribute(edge_kernel_m, cudaFuncAttributeMaxDynamicSharedMemorySize, EDGE_SMEM);

    detect_kernel<<<1, 32>>>((const int*)ei);
    convert_kernel<<<(N_EDGES + 255) / 256, 256>>>(ei);
    zero_kernel<<<2048, 256>>>();
    prep_kernel<<<64, 256>>>(We1, We2);
    edge_kernel_m<<<N_EDGES / 256, 256, EDGE_SMEM>>>(h, ea, be1, be2);
    node_kernel<<<(N_NODES + 63) / 64, 256>>>(h, Wh1, bh1, Wh2, bh2, out);
}

// round 4
// speedup vs baseline: 4.4173x; 1.0352x over previous
#include <cuda_runtime.h>
#include <cstdint>

#define N_NODES 50000
#define N_EDGES 800000
#define DNODE   128
#define DEDGE   32
#define HID     128

typedef unsigned long long u64;

// ---------------- device-global scratch (no allocations allowed) ----------------
__device__ int   g_src[N_EDGES];
__device__ int   g_dst[N_EDGES];
__device__ float g_mi[(size_t)N_NODES * HID];      // 25.6 MB scatter target
__device__ float g_P[(size_t)N_NODES * 256];       // 51.2 MB: [h@W1a | h@W1b]
__device__ float g_W1r[288 * 128];                 // We1, tf32-rounded, [K][N]
__device__ float g_W2r[128 * 128];                 // We2, tf32-rounded, [K][N]
__device__ int   g_is64;

// ---------------- helpers ----------------
__device__ __forceinline__ uint32_t smem_u32(const void* p) {
    uint32_t a;
    asm("{ .reg .u64 t; cvta.to.shared.u64 t, %1; cvt.u32.u64 %0, t; }" : "=r"(a) : "l"(p));
    return a;
}
__device__ __forceinline__ uint32_t rna(float x) {
    uint32_t r; asm("cvt.rna.tf32.f32 %0, %1;" : "=r"(r) : "f"(x)); return r;
}
__device__ __forceinline__ u64 pk2(float lo, float hi) {
    u64 r; asm("mov.b64 %0, {%1, %2};" : "=l"(r) : "f"(lo), "f"(hi)); return r;
}
__device__ __forceinline__ void fma2(u64& d, u64 a, u64 b) {
    asm("fma.rn.f32x2 %0, %1, %2, %0;" : "+l"(d) : "l"(a), "l"(b));
}
__device__ __forceinline__ float2 upk2(u64 v) {
    float2 f; asm("mov.b64 {%0, %1}, %2;" : "=f"(f.x), "=f"(f.y) : "l"(v)); return f;
}

#define CP_ASYNC(ds, gp) \
    asm volatile("cp.async.cg.shared.global [%0], [%1], 16;" :: "r"(ds), "l"(gp))
#define CP_COMMIT() asm volatile("cp.async.commit_group;" ::: "memory")
#define CP_WAIT1()  asm volatile("cp.async.wait_group 1;" ::: "memory")
#define CP_WAIT0()  asm volatile("cp.async.wait_group 0;" ::: "memory")

#define MMA_TF32(C, a0, a1, a2, a3, b0, b1) \
    asm volatile("mma.sync.aligned.m16n8k8.row.col.f32.tf32.tf32.f32 " \
        "{%0,%1,%2,%3}, {%4,%5,%6,%7}, {%8,%9}, {%0,%1,%2,%3};" \
        : "+f"((C)[0]), "+f"((C)[1]), "+f"((C)[2]), "+f"((C)[3]) \
        : "r"(a0), "r"(a1), "r"(a2), "r"(a3), "r"(b0), "r"(b1))

// ---------------- aux kernels ----------------
__global__ void detect_kernel(const int* __restrict__ ei) {
    if (threadIdx.x == 0) {
        int all0 = 1;
        for (int s = 0; s < 512; s++)
            if (ei[2 * s + 1] != 0) { all0 = 0; break; }
        g_is64 = all0;
    }
}

__global__ void convert_kernel(const void* __restrict__ ei) {
    int i = blockIdx.x * blockDim.x + threadIdx.x;
    if (i >= N_EDGES) return;
    if (g_is64) {
        const long long* p = (const long long*)ei;
        g_src[i] = (int)p[i];
        g_dst[i] = (int)p[N_EDGES + i];
    } else {
        const int* p = (const int*)ei;
        g_src[i] = p[i];
        g_dst[i] = p[N_EDGES + i];
    }
}

__global__ void zero_kernel() {
    size_t n = (size_t)N_NODES * HID;
    for (size_t i = (size_t)blockIdx.x * blockDim.x + threadIdx.x; i < n;
         i += (size_t)gridDim.x * blockDim.x)
        g_mi[i] = 0.0f;
}

__global__ void prep_kernel(const float* __restrict__ W1, const float* __restrict__ W2) {
    int t = blockIdx.x * blockDim.x + threadIdx.x;
    int stride = gridDim.x * blockDim.x;
    for (int i = t; i < 288 * 128; i += stride)
        g_W1r[i] = __uint_as_float(rna(W1[i]));
    for (int i = t; i < 128 * 128; i += stride)
        g_W2r[i] = __uint_as_float(rna(W2[i]));
}

// =================================================================
// Precompute P = h @ [We1_a | We1_b]  (50k x 128 x 256, tf32 mma)
// Block: 128 rows x 256 cols, 8 warps (2m x 4n), warp tile 64x64.
// smem: X 2x16KB @ [0,32768), W 2x32KB @ [32768,98304)
// =================================================================
#define GP_SMEM 98304

__global__ __launch_bounds__(256) void gemm_P(const float* __restrict__ h) {
    extern __shared__ char sm[];
    const uint32_t smb = smem_u32(sm);
    const int tid = threadIdx.x, lane = tid & 31, wid = tid >> 5;
    const int g = lane >> 2, t4 = lane & 3;
    const int m0 = (wid >> 2) * 64, n0 = (wid & 3) * 64;
    const int r0 = blockIdx.x * 128;

    auto issue_x = [&](int ch, int b) {
        uint32_t xb = smb + b * 16384;
#pragma unroll
        for (int i = 0; i < 4; i++) {
            int f = tid + i * 256;
            int row = f >> 3, q = f & 7;
            int gr = r0 + row; if (gr >= N_NODES) gr = 0;
            const float* gp = h + (size_t)gr * DNODE + ch * 32 + q * 4;
            uint32_t ds = xb + 4u * (uint32_t)(row * 32 + ((4 * q) ^ (4 * (row & 7))));
            CP_ASYNC(ds, gp);
        }
    };
    auto issue_w = [&](int ch, int b) {
        uint32_t wb = smb + 32768 + b * 32768;
#pragma unroll
        for (int i = 0; i < 8; i++) {
            int f = tid + i * 256;
            int k = f >> 6, n4 = f & 63;
            int n = 4 * n4;
            const float* gp = (n < 128)
                ? g_W1r + (size_t)(ch * 32 + k) * 128 + n
                : g_W1r + (size_t)(128 + ch * 32 + k) * 128 + (n - 128);
            uint32_t ds = wb + 4u * (uint32_t)(k * 256 + (n ^ (8 * (k & 3))));
            CP_ASYNC(ds, gp);
        }
    };

    float c[4][8][4];
#pragma unroll
    for (int mf = 0; mf < 4; mf++)
#pragma unroll
        for (int nf = 0; nf < 8; nf++)
#pragma unroll
            for (int j = 0; j < 4; j++) c[mf][nf][j] = 0.0f;

    issue_x(0, 0); issue_w(0, 0); CP_COMMIT();
    for (int ch = 0; ch < 4; ch++) {
        if (ch < 3) {
            issue_x(ch + 1, (ch + 1) & 1);
            issue_w(ch + 1, (ch + 1) & 1);
            CP_COMMIT(); CP_WAIT1();
        } else CP_WAIT0();
        __syncthreads();
        const uint32_t* Xw = (const uint32_t*)sm + (ch & 1) * 4096;
        const uint32_t* Ww = (const uint32_t*)(sm + 32768) + (ch & 1) * 8192;
#pragma unroll
        for (int s = 0; s < 4; s++) {
            const int kb = 8 * s + t4;
            uint32_t b0r[8], b1r[8];
#pragma unroll
            for (int nf = 0; nf < 8; nf++) {
                int wc = (n0 + 8 * nf + g) ^ (8 * t4);
                b0r[nf] = Ww[kb * 256 + wc];
                b1r[nf] = Ww[(kb + 4) * 256 + wc];
            }
#pragma unroll
            for (int mf = 0; mf < 4; mf++) {
                int base = (m0 + mf * 16 + g) * 32;
                uint32_t a0 = Xw[base + (kb ^ (4 * g))];
                uint32_t a1 = Xw[base + 8 * 32 + (kb ^ (4 * g))];
                uint32_t a2 = Xw[base + ((kb + 4) ^ (4 * g))];
                uint32_t a3 = Xw[base + 8 * 32 + ((kb + 4) ^ (4 * g))];
#pragma unroll
                for (int nf = 0; nf < 8; nf++)
                    MMA_TF32(c[mf][nf], a0, a1, a2, a3, b0r[nf], b1r[nf]);
            }
        }
        __syncthreads();
    }

#pragma unroll
    for (int mf = 0; mf < 4; mf++) {
        int r = m0 + mf * 16 + g;
#pragma unroll
        for (int nf = 0; nf < 8; nf++) {
            int col = n0 + 8 * nf + 2 * t4;
            if (r0 + r < N_NODES)
                *(float2*)(g_P + (size_t)(r0 + r) * 256 + col) =
                    make_float2(c[mf][nf][0], c[mf][nf][1]);
            if (r0 + r + 8 < N_NODES)
                *(float2*)(g_P + (size_t)(r0 + r + 8) * 256 + col) =
                    make_float2(c[mf][nf][2], c[mf][nf][3]);
        }
    }
}

// =================================================================
// Edge kernel v2: layer 1 collapsed to K=32 (ea @ We1_e) + P-gather merge.
// Block = 256 threads (8 warps), 256 edges, warp tile 64x64.
// smem map (bytes):
//   [0, 131072)       Ys: 256 rows x 128 words (X ea-chunk overlays [0,32768))
//   [131072, 163840)  Wbuf0/Wbuf1 (16 KB each)
//   [163840, 164352)  sb1   [164352, 164864) sb2
//   [164864, 165888)  sSrc  [165888, 166912) sDst
// =================================================================
#define EDGE_SMEM 166912

__global__ __launch_bounds__(256, 1) void edge_kernel_m(
    const float* __restrict__ ea,
    const float* __restrict__ b1g, const float* __restrict__ b2g)
{
    extern __shared__ char sm[];
    const uint32_t smb = smem_u32(sm);
    float* Ys  = (float*)sm;
    float* sb1 = (float*)(sm + 163840);
    float* sb2 = (float*)(sm + 164352);
    int*   sSrc = (int*)(sm + 164864);
    int*   sDst = (int*)(sm + 165888);

    const int tid  = threadIdx.x;
    const int lane = tid & 31, wid = tid >> 5;
    const int g    = lane >> 2, t4 = lane & 3;
    const int m0   = (wid >> 1) * 64;
    const int n0   = (wid & 1) * 64;
    const int e0   = blockIdx.x * 256;

    if (tid < 128) { sb1[tid] = b1g[tid]; sb2[tid] = b2g[tid]; }
    sSrc[tid] = g_src[e0 + tid];
    sDst[tid] = g_dst[e0 + tid];

    // issue ea chunk (256 rows x 32 floats) into X region [0,32768)
#pragma unroll
    for (int i = 0; i < 8; i++) {
        int f = tid + i * 256;
        int row = f >> 3, q = f & 7;
        const float* gp = ea + (size_t)(e0 + row) * DEDGE + q * 4;
        uint32_t ds = smb + 4u * (uint32_t)(row * 32 + ((4 * q) ^ (4 * (row & 7))));
        CP_ASYNC(ds, gp);
    }
    // issue W1e chunk (We1 rows 256..287) into Wbuf0
    auto issue_w = [&](const float* W, int ch, int wb) {
        uint32_t wbase = smb + 131072 + wb * 16384;
#pragma unroll
        for (int i = 0; i < 4; i++) {
            int f = tid + i * 256;
            int k = f >> 5, n4 = f & 31;
            const float* gp = W + (size_t)(ch * 32 + k) * 128 + n4 * 4;
            uint32_t ds = wbase + 4u * (uint32_t)(k * 128 + ((4 * n4) ^ (8 * (k & 3))));
            CP_ASYNC(ds, gp);
        }
    };
    issue_w(g_W1r, 8, 0);
    CP_COMMIT();

    float c[4][8][4];
#pragma unroll
    for (int mf = 0; mf < 4; mf++)
#pragma unroll
        for (int nf = 0; nf < 8; nf++)
#pragma unroll
            for (int j = 0; j < 4; j++) c[mf][nf][j] = 0.0f;

    auto compute = [&](const uint32_t* Xw, int rstride, int cofs, const uint32_t* Ww) {
#pragma unroll
        for (int s = 0; s < 4; s++) {
            const int kb = 8 * s + t4;
            uint32_t b0r[8], b1r[8];
#pragma unroll
            for (int nf = 0; nf < 8; nf++) {
                int wc = (n0 + 8 * nf + g) ^ (8 * t4);
                b0r[nf] = Ww[kb * 128 + wc];
                b1r[nf] = Ww[(kb + 4) * 128 + wc];
            }
#pragma unroll
            for (int mf = 0; mf < 4; mf++) {
                int base = (m0 + mf * 16 + g) * rstride + cofs;
                uint32_t a0 = Xw[base + (kb ^ (4 * g))];
                uint32_t a1 = Xw[base + 8 * rstride + (kb ^ (4 * g))];
                uint32_t a2 = Xw[base + ((kb + 4) ^ (4 * g))];
                uint32_t a3 = Xw[base + 8 * rstride + ((kb + 4) ^ (4 * g))];
#pragma unroll
                for (int nf = 0; nf < 8; nf++)
                    MMA_TF32(c[mf][nf], a0, a1, a2, a3, b0r[nf], b1r[nf]);
            }
        }
    };

    // ======== phase 1: T = ea @ We1_e (single K=32 chunk) ========
    CP_WAIT0();
    __syncthreads();
    compute((const uint32_t*)sm, 32, 0, (const uint32_t*)(sm + 131072));
    __syncthreads();

    // epilogue A: write raw T into Ys, zero accumulators
#pragma unroll
    for (int mf = 0; mf < 4; mf++) {
        int r0r = m0 + mf * 16 + g;
#pragma unroll
        for (int nf = 0; nf < 8; nf++) {
            int cc = n0 + 8 * nf + 2 * t4;
            int w = (cc & ~31) + ((cc & 31) ^ (4 * g));
            *(float2*)&Ys[r0r * 128 + w]       = make_float2(c[mf][nf][0], c[mf][nf][1]);
            *(float2*)&Ys[(r0r + 8) * 128 + w] = make_float2(c[mf][nf][2], c[mf][nf][3]);
#pragma unroll
            for (int j = 0; j < 4; j++) c[mf][nf][j] = 0.0f;
        }
    }
    // prefetch W2 chunk 0 (overlaps P-merge)
    issue_w(g_W2r, 0, 0); CP_COMMIT();
    __syncthreads();

    // ---- P-merge: Y = relu(T + P[src].lo + P[dst].hi + b1) ----
#pragma unroll 4
    for (int i = 0; i < 32; i++) {
        int f = tid + i * 256;
        int row = f >> 5, c4 = f & 31;
        int w = row * 128 + (c4 >> 3) * 32 + ((4 * (c4 & 7)) ^ (4 * (row & 7)));
        float4 t = *(const float4*)&Ys[w];
        float4 ps = *(const float4*)(g_P + (size_t)sSrc[row] * 256 + 4 * c4);
        float4 pd = *(const float4*)(g_P + (size_t)sDst[row] * 256 + 128 + 4 * c4);
        float4 b = *(const float4*)&sb1[4 * c4];
        float4 y;
        y.x = fmaxf(t.x + ps.x + pd.x + b.x, 0.0f);
        y.y = fmaxf(t.y + ps.y + pd.y + b.y, 0.0f);
        y.z = fmaxf(t.z + ps.z + pd.z + b.z, 0.0f);
        y.w = fmaxf(t.w + ps.w + pd.w + b.w, 0.0f);
        *(float4*)&Ys[w] = y;
    }

    // ======== phase 2: layer 2, K = 128 = 4 chunks of 32 (A from Ys) ========
    for (int ch = 0; ch < 4; ch++) {
        if (ch < 3) {
            issue_w(g_W2r, ch + 1, (ch + 1) & 1);
            CP_COMMIT(); CP_WAIT1();
        } else CP_WAIT0();
        __syncthreads();
        compute((const uint32_t*)sm, 128, ch * 32,
                (const uint32_t*)(sm + 131072) + (ch & 1) * 4096);
        __syncthreads();
    }

    // ---- stage messages (+bias b2) into Ys ----
#pragma unroll
    for (int mf = 0; mf < 4; mf++) {
        int r0r = m0 + mf * 16 + g;
#pragma unroll
        for (int nf = 0; nf < 8; nf++) {
            int cc = n0 + 8 * nf + 2 * t4;
            float bb0 = sb2[cc], bb1 = sb2[cc + 1];
            int w = (cc & ~31) + ((cc & 31) ^ (4 * g));
            *(float2*)&Ys[r0r * 128 + w] =
                make_float2(c[mf][nf][0] + bb0, c[mf][nf][1] + bb1);
            *(float2*)&Ys[(r0r + 8) * 128 + w] =
                make_float2(c[mf][nf][2] + bb0, c[mf][nf][3] + bb1);
        }
    }
    __syncthreads();

    // ---- coalesced vectorized scatter-add ----
#pragma unroll 4
    for (int i = 0; i < 32; i++) {
        int f = tid + i * 256;
        int row = f >> 5, c4 = f & 31;
        int w = row * 128 + (c4 >> 3) * 32 + ((4 * (c4 & 7)) ^ (4 * (row & 7)));
        float4 v = *(const float4*)&Ys[w];
        float* gp = g_mi + (size_t)sDst[row] * HID + 4 * c4;
        asm volatile("red.global.add.v4.f32 [%0], {%1,%2,%3,%4};"
                     :: "l"(gp), "f"(v.x), "f"(v.y), "f"(v.z), "f"(v.w) : "memory");
    }
}

// =================================================================
// Node MLP kernel (fp32 FFMA2, unchanged — exact math on m_i)
// =================================================================
__global__ __launch_bounds__(256) void node_kernel(
    const float* __restrict__ h,
    const float* __restrict__ W1, const float* __restrict__ b1,
    const float* __restrict__ W2, const float* __restrict__ b2,
    float* __restrict__ out)
{
    __shared__ float Xs[64][17];
    __shared__ float Ws[16][128];
    __shared__ float Ys2[64][129];

    const int t  = threadIdx.x;
    const int r0 = blockIdx.x * 64;
    const int tx = t & 15, ty = t >> 4;
    const int eb = ty * 4, cb = tx * 8;

    u64 acc[4][4];
#pragma unroll
    for (int j = 0; j < 4; j++) {
        u64 bj = pk2(b1[cb + 2 * j], b1[cb + 2 * j + 1]);
        acc[0][j] = bj; acc[1][j] = bj; acc[2][j] = bj; acc[3][j] = bj;
    }

    const int le = t >> 2, lj = t & 3;
    const int lr = (r0 + le < N_NODES) ? (r0 + le) : 0;

    for (int ch = 0; ch < 16; ch++) {
        const float* p;
        if (ch < 8) p = h    + (size_t)lr * DNODE + ch * 16;
        else        p = g_mi + (size_t)lr * HID   + (ch - 8) * 16;
        float4 v = *(const float4*)(p + lj * 4);

        const float* wsrc = W1 + (size_t)ch * 16 * 128;
#pragma unroll
        for (int r2 = 0; r2 < 2; r2++) {
            int f = t + r2 * 256;
            int rw = f >> 5, c = (f & 31) * 4;
            *(float4*)&Ws[rw][c] = *(const float4*)(wsrc + rw * 128 + c);
        }
        Xs[le][lj * 4 + 0] = v.x; Xs[le][lj * 4 + 1] = v.y;
        Xs[le][lj * 4 + 2] = v.z; Xs[le][lj * 4 + 3] = v.w;
        __syncthreads();

#pragma unroll
        for (int kk = 0; kk < 16; kk++) {
            ulonglong2 w01 = *(const ulonglong2*)&Ws[kk][cb];
            ulonglong2 w23 = *(const ulonglong2*)&Ws[kk][cb + 4];
            float a0 = Xs[eb + 0][kk], a1 = Xs[eb + 1][kk];
            float a2 = Xs[eb + 2][kk], a3 = Xs[eb + 3][kk];
            u64 A0 = pk2(a0, a0), A1 = pk2(a1, a1), A2 = pk2(a2, a2), A3 = pk2(a3, a3);
            fma2(acc[0][0], A0, w01.x); fma2(acc[0][1], A0, w01.y);
            fma2(acc[0][2], A0, w23.x); fma2(acc[0][3], A0, w23.y);
            fma2(acc[1][0], A1, w01.x); fma2(acc[1][1], A1, w01.y);
            fma2(acc[1][2], A1, w23.x); fma2(acc[1][3], A1, w23.y);
            fma2(acc[2][0], A2, w01.x); fma2(acc[2][1], A2, w01.y);
            fma2(acc[2][2], A2, w23.x); fma2(acc[2][3], A2, w23.y);
            fma2(acc[3][0], A3, w01.x); fma2(acc[3][1], A3, w01.y);
            fma2(acc[3][2], A3, w23.x); fma2(acc[3][3], A3, w23.y);
        }
        __syncthreads();
    }

#pragma unroll
    for (int i = 0; i < 4; i++)
#pragma unroll
        for (int j = 0; j < 4; j++) {
            float2 v = upk2(acc[i][j]);
            Ys2[eb + i][cb + 2 * j]     = fmaxf(v.x, 0.0f);
            Ys2[eb + i][cb + 2 * j + 1] = fmaxf(v.y, 0.0f);
        }
#pragma unroll
    for (int j = 0; j < 4; j++) {
        u64 bj = pk2(b2[cb + 2 * j], b2[cb + 2 * j + 1]);
        acc[0][j] = bj; acc[1][j] = bj; acc[2][j] = bj; acc[3][j] = bj;
    }
    __syncthreads();

    for (int ch = 0; ch < 8; ch++) {
        const float* wsrc = W2 + (size_t)ch * 16 * 128;
#pragma unroll
        for (int r2 = 0; r2 < 2; r2++) {
            int f = t + r2 * 256;
            int rw = f >> 5, c = (f & 31) * 4;
            *(float4*)&Ws[rw][c] = *(const float4*)(wsrc + rw * 128 + c);
        }
        __syncthreads();
#pragma unroll
        for (int kk = 0; kk < 16; kk++) {
            int k = ch * 16 + kk;
            ulonglong2 w01 = *(const ulonglong2*)&Ws[kk][cb];
            ulonglong2 w23 = *(const ulonglong2*)&Ws[kk][cb + 4];
            float a0 = Ys2[eb + 0][k], a1 = Ys2[eb + 1][k];
            float a2 = Ys2[eb + 2][k], a3 = Ys2[eb + 3][k];
            u64 A0 = pk2(a0, a0), A1 = pk2(a1, a1), A2 = pk2(a2, a2), A3 = pk2(a3, a3);
            fma2(acc[0][0], A0, w01.x); fma2(acc[0][1], A0, w01.y);
            fma2(acc[0][2], A0, w23.x); fma2(acc[0][3], A0, w23.y);
            fma2(acc[1][0], A1, w01.x); fma2(acc[1][1], A1, w01.y);
            fma2(acc[1][2], A1, w23.x); fma2(acc[1][3], A1, w23.y);
            fma2(acc[2][0], A2, w01.x); fma2(acc[2][1], A2, w01.y);
            fma2(acc[2][2], A2, w23.x); fma2(acc[2][3], A2, w23.y);
            fma2(acc[3][0], A3, w01.x); fma2(acc[3][1], A3, w01.y);
            fma2(acc[3][2], A3, w23.x); fma2(acc[3][3], A3, w23.y);
        }
        __syncthreads();
    }

#pragma unroll
    for (int i = 0; i < 4; i++) {
        int rw = r0 + eb + i;
        if (rw < N_NODES) {
            float* op = out + (size_t)rw * 128 + cb;
#pragma unroll
            for (int j = 0; j < 4; j++) {
                float2 v = upk2(acc[i][j]);
                op[2 * j]     = v.x;
                op[2 * j + 1] = v.y;
            }
        }
    }
}

// =================================================================
extern "C" void kernel_launch(void* const* d_in, const int* in_sizes, int n_in,
                              void* d_out, int out_size) {
    const float* h   = (const float*)d_in[0];
    const void*  ei  = d_in[1];
    const float* ea  = (const float*)d_in[2];
    const float* We1 = (const float*)d_in[3];
    const float* be1 = (const float*)d_in[4];
    const float* We2 = (const float*)d_in[5];
    const float* be2 = (const float*)d_in[6];
    const float* Wh1 = (const float*)d_in[7];
    const float* bh1 = (const float*)d_in[8];
    const float* Wh2 = (const float*)d_in[9];
    const float* bh2 = (const float*)d_in[10];
    float* out = (float*)d_out;

    cudaFuncSetAttribute(edge_kernel_m, cudaFuncAttributeMaxDynamicSharedMemorySize, EDGE_SMEM);
    cudaFuncSetAttribute(gemm_P, cudaFuncAttributeMaxDynamicSharedMemorySize, GP_SMEM);

    detect_kernel<<<1, 32>>>((const int*)ei);
    convert_kernel<<<(N_EDGES + 255) / 256, 256>>>(ei);
    zero_kernel<<<2048, 256>>>();
    prep_kernel<<<64, 256>>>(We1, We2);
    gemm_P<<<(N_NODES + 127) / 128, 256, GP_SMEM>>>(h);
    edge_kernel_m<<<N_EDGES / 256, 256, EDGE_SMEM>>>(ea, be1, be2);
    node_kernel<<<(N_NODES + 63) / 64, 256>>>(h, Wh1, bh1, Wh2, bh2, out);
}

// round 5
// speedup vs baseline: 5.2634x; 1.1915x over previous
#include <cuda_runtime.h>
#include <cstdint>

#define N_NODES 50000
#define N_EDGES 800000
#define DNODE   128
#define DEDGE   32
#define HID     128

typedef unsigned long long u64;

// ---------------- device-global scratch (no allocations allowed) ----------------
__device__ int   g_src[N_EDGES];
__device__ int   g_dst[N_EDGES];
__device__ float g_mi[(size_t)N_NODES * HID];      // 25.6 MB scatter target
__device__ float g_P[(size_t)N_NODES * 256];       // 51.2 MB: [h@W1a | h@W1b]
__device__ float g_W1r[288 * 128];                 // We1, tf32-rounded, [K][N]
__device__ float g_W2r[128 * 128];                 // We2, tf32-rounded, [K][N]
__device__ int   g_is64;

// ---------------- helpers ----------------
__device__ __forceinline__ uint32_t smem_u32(const void* p) {
    uint32_t a;
    asm("{ .reg .u64 t; cvta.to.shared.u64 t, %1; cvt.u32.u64 %0, t; }" : "=r"(a) : "l"(p));
    return a;
}
__device__ __forceinline__ uint32_t rna(float x) {
    uint32_t r; asm("cvt.rna.tf32.f32 %0, %1;" : "=r"(r) : "f"(x)); return r;
}
__device__ __forceinline__ u64 pk2(float lo, float hi) {
    u64 r; asm("mov.b64 %0, {%1, %2};" : "=l"(r) : "f"(lo), "f"(hi)); return r;
}
__device__ __forceinline__ void fma2(u64& d, u64 a, u64 b) {
    asm("fma.rn.f32x2 %0, %1, %2, %0;" : "+l"(d) : "l"(a), "l"(b));
}
__device__ __forceinline__ float2 upk2(u64 v) {
    float2 f; asm("mov.b64 {%0, %1}, %2;" : "=f"(f.x), "=f"(f.y) : "l"(v)); return f;
}

#define CP_ASYNC(ds, gp) \
    asm volatile("cp.async.cg.shared.global [%0], [%1], 16;" :: "r"(ds), "l"(gp))
#define CP_COMMIT() asm volatile("cp.async.commit_group;" ::: "memory")
#define CP_WAIT1()  asm volatile("cp.async.wait_group 1;" ::: "memory")
#define CP_WAIT0()  asm volatile("cp.async.wait_group 0;" ::: "memory")

#define MMA_TF32(C, a0, a1, a2, a3, b0, b1) \
    asm volatile("mma.sync.aligned.m16n8k8.row.col.f32.tf32.tf32.f32 " \
        "{%0,%1,%2,%3}, {%4,%5,%6,%7}, {%8,%9}, {%0,%1,%2,%3};" \
        : "+f"((C)[0]), "+f"((C)[1]), "+f"((C)[2]), "+f"((C)[3]) \
        : "r"(a0), "r"(a1), "r"(a2), "r"(a3), "r"(b0), "r"(b1))

// ---------------- aux kernels ----------------
__global__ void detect_kernel(const int* __restrict__ ei) {
    if (threadIdx.x == 0) {
        int all0 = 1;
        for (int s = 0; s < 512; s++)
            if (ei[2 * s + 1] != 0) { all0 = 0; break; }
        g_is64 = all0;
    }
}

__global__ void convert_kernel(const void* __restrict__ ei) {
    int i = blockIdx.x * blockDim.x + threadIdx.x;
    if (i >= N_EDGES) return;
    if (g_is64) {
        const long long* p = (const long long*)ei;
        g_src[i] = (int)p[i];
        g_dst[i] = (int)p[N_EDGES + i];
    } else {
        const int* p = (const int*)ei;
        g_src[i] = p[i];
        g_dst[i] = p[N_EDGES + i];
    }
}

__global__ void zero_kernel() {
    size_t n = (size_t)N_NODES * HID;
    for (size_t i = (size_t)blockIdx.x * blockDim.x + threadIdx.x; i < n;
         i += (size_t)gridDim.x * blockDim.x)
        g_mi[i] = 0.0f;
}

__global__ void prep_kernel(const float* __restrict__ W1, const float* __restrict__ W2) {
    int t = blockIdx.x * blockDim.x + threadIdx.x;
    int stride = gridDim.x * blockDim.x;
    for (int i = t; i < 288 * 128; i += stride)
        g_W1r[i] = __uint_as_float(rna(W1[i]));
    for (int i = t; i < 128 * 128; i += stride)
        g_W2r[i] = __uint_as_float(rna(W2[i]));
}

// =================================================================
// Precompute P = h @ [We1_a | We1_b]  (50k x 128 x 256, tf32 mma)
// Block: 128 rows x 256 cols, 8 warps (2m x 4n), warp tile 64x64.
// smem: X 2x16KB @ [0,32768), W 2x32KB @ [32768,98304)
// =================================================================
#define GP_SMEM 98304

__global__ __launch_bounds__(256) void gemm_P(const float* __restrict__ h) {
    extern __shared__ char sm[];
    const uint32_t smb = smem_u32(sm);
    const int tid = threadIdx.x, lane = tid & 31, wid = tid >> 5;
    const int g = lane >> 2, t4 = lane & 3;
    const int m0 = (wid >> 2) * 64, n0 = (wid & 3) * 64;
    const int r0 = blockIdx.x * 128;

    auto issue_x = [&](int ch, int b) {
        uint32_t xb = smb + b * 16384;
#pragma unroll
        for (int i = 0; i < 4; i++) {
            int f = tid + i * 256;
            int row = f >> 3, q = f & 7;
            int gr = r0 + row; if (gr >= N_NODES) gr = 0;
            const float* gp = h + (size_t)gr * DNODE + ch * 32 + q * 4;
            uint32_t ds = xb + 4u * (uint32_t)(row * 32 + ((4 * q) ^ (4 * (row & 7))));
            CP_ASYNC(ds, gp);
        }
    };
    auto issue_w = [&](int ch, int b) {
        uint32_t wb = smb + 32768 + b * 32768;
#pragma unroll
        for (int i = 0; i < 8; i++) {
            int f = tid + i * 256;
            int k = f >> 6, n4 = f & 63;
            int n = 4 * n4;
            const float* gp = (n < 128)
                ? g_W1r + (size_t)(ch * 32 + k) * 128 + n
                : g_W1r + (size_t)(128 + ch * 32 + k) * 128 + (n - 128);
            uint32_t ds = wb + 4u * (uint32_t)(k * 256 + (n ^ (8 * (k & 3))));
            CP_ASYNC(ds, gp);
        }
    };

    float c[4][8][4];
#pragma unroll
    for (int mf = 0; mf < 4; mf++)
#pragma unroll
        for (int nf = 0; nf < 8; nf++)
#pragma unroll
            for (int j = 0; j < 4; j++) c[mf][nf][j] = 0.0f;

    issue_x(0, 0); issue_w(0, 0); CP_COMMIT();
    for (int ch = 0; ch < 4; ch++) {
        if (ch < 3) {
            issue_x(ch + 1, (ch + 1) & 1);
            issue_w(ch + 1, (ch + 1) & 1);
            CP_COMMIT(); CP_WAIT1();
        } else CP_WAIT0();
        __syncthreads();
        const uint32_t* Xw = (const uint32_t*)sm + (ch & 1) * 4096;
        const uint32_t* Ww = (const uint32_t*)(sm + 32768) + (ch & 1) * 8192;
#pragma unroll
        for (int s = 0; s < 4; s++) {
            const int kb = 8 * s + t4;
            uint32_t b0r[8], b1r[8];
#pragma unroll
            for (int nf = 0; nf < 8; nf++) {
                int wc = (n0 + 8 * nf + g) ^ (8 * t4);
                b0r[nf] = Ww[kb * 256 + wc];
                b1r[nf] = Ww[(kb + 4) * 256 + wc];
            }
#pragma unroll
            for (int mf = 0; mf < 4; mf++) {
                int base = (m0 + mf * 16 + g) * 32;
                uint32_t a0 = Xw[base + (kb ^ (4 * g))];
                uint32_t a1 = Xw[base + 8 * 32 + (kb ^ (4 * g))];
                uint32_t a2 = Xw[base + ((kb + 4) ^ (4 * g))];
                uint32_t a3 = Xw[base + 8 * 32 + ((kb + 4) ^ (4 * g))];
#pragma unroll
                for (int nf = 0; nf < 8; nf++)
                    MMA_TF32(c[mf][nf], a0, a1, a2, a3, b0r[nf], b1r[nf]);
            }
        }
        __syncthreads();
    }

#pragma unroll
    for (int mf = 0; mf < 4; mf++) {
        int r = m0 + mf * 16 + g;
#pragma unroll
        for (int nf = 0; nf < 8; nf++) {
            int col = n0 + 8 * nf + 2 * t4;
            if (r0 + r < N_NODES)
                *(float2*)(g_P + (size_t)(r0 + r) * 256 + col) =
                    make_float2(c[mf][nf][0], c[mf][nf][1]);
            if (r0 + r + 8 < N_NODES)
                *(float2*)(g_P + (size_t)(r0 + r + 8) * 256 + col) =
                    make_float2(c[mf][nf][2], c[mf][nf][3]);
        }
    }
}

// =================================================================
// Edge kernel v3: 128 edges/block, ~100KB smem -> 2 CTAs/SM.
// 8 warps: 4m x 2n, warp tile 32x64. c[2][8][4].
// smem map (bytes):
//   [0, 65536)       Ys: 128 rows x 128 words (X ea-chunk overlays [0,16384))
//   [65536, 98304)   Wbuf0/Wbuf1 (16 KB each)
//   [98304, 98816)   sb1   [98816, 99328)  sb2
//   [99328, 99840)   sSrc  [99840, 100352) sDst
// =================================================================
#define EDGE_SMEM 100352

__global__ __launch_bounds__(256, 2) void edge_kernel_m(
    const float* __restrict__ ea,
    const float* __restrict__ b1g, const float* __restrict__ b2g)
{
    extern __shared__ char sm[];
    const uint32_t smb = smem_u32(sm);
    float* Ys  = (float*)sm;
    float* sb1 = (float*)(sm + 98304);
    float* sb2 = (float*)(sm + 98816);
    int*   sSrc = (int*)(sm + 99328);
    int*   sDst = (int*)(sm + 99840);

    const int tid  = threadIdx.x;
    const int lane = tid & 31, wid = tid >> 5;
    const int g    = lane >> 2, t4 = lane & 3;
    const int m0   = (wid >> 1) * 32;     // warp M offset (edges), 4 m-warps
    const int n0   = (wid & 1) * 64;      // warp N offset (cols), 2 n-warps
    const int e0   = blockIdx.x * 128;

    if (tid < 128) {
        sb1[tid] = b1g[tid];
        sb2[tid] = b2g[tid];
        sSrc[tid] = g_src[e0 + tid];
        sDst[tid] = g_dst[e0 + tid];
    }

    // issue ea chunk (128 rows x 32 floats) into X region [0,16384)
#pragma unroll
    for (int i = 0; i < 4; i++) {
        int f = tid + i * 256;
        int row = f >> 3, q = f & 7;
        const float* gp = ea + (size_t)(e0 + row) * DEDGE + q * 4;
        uint32_t ds = smb + 4u * (uint32_t)(row * 32 + ((4 * q) ^ (4 * (row & 7))));
        CP_ASYNC(ds, gp);
    }
    auto issue_w = [&](const float* W, int ch, int wb) {
        uint32_t wbase = smb + 65536 + wb * 16384;
#pragma unroll
        for (int i = 0; i < 4; i++) {
            int f = tid + i * 256;
            int k = f >> 5, n4 = f & 31;
            const float* gp = W + (size_t)(ch * 32 + k) * 128 + n4 * 4;
            uint32_t ds = wbase + 4u * (uint32_t)(k * 128 + ((4 * n4) ^ (8 * (k & 3))));
            CP_ASYNC(ds, gp);
        }
    };
    issue_w(g_W1r, 8, 0);   // We1 rows 256..287 (edge-attr slice)
    CP_COMMIT();

    float c[2][8][4];
#pragma unroll
    for (int mf = 0; mf < 2; mf++)
#pragma unroll
        for (int nf = 0; nf < 8; nf++)
#pragma unroll
            for (int j = 0; j < 4; j++) c[mf][nf][j] = 0.0f;

    auto compute = [&](const uint32_t* Xw, int rstride, int cofs, const uint32_t* Ww) {
#pragma unroll
        for (int s = 0; s < 4; s++) {
            const int kb = 8 * s + t4;
            uint32_t b0r[8], b1r[8];
#pragma unroll
            for (int nf = 0; nf < 8; nf++) {
                int wc = (n0 + 8 * nf + g) ^ (8 * t4);
                b0r[nf] = Ww[kb * 128 + wc];
                b1r[nf] = Ww[(kb + 4) * 128 + wc];
            }
#pragma unroll
            for (int mf = 0; mf < 2; mf++) {
                int base = (m0 + mf * 16 + g) * rstride + cofs;
                uint32_t a0 = Xw[base + (kb ^ (4 * g))];
                uint32_t a1 = Xw[base + 8 * rstride + (kb ^ (4 * g))];
                uint32_t a2 = Xw[base + ((kb + 4) ^ (4 * g))];
                uint32_t a3 = Xw[base + 8 * rstride + ((kb + 4) ^ (4 * g))];
#pragma unroll
                for (int nf = 0; nf < 8; nf++)
                    MMA_TF32(c[mf][nf], a0, a1, a2, a3, b0r[nf], b1r[nf]);
            }
        }
    };

    // ======== phase 1: T = ea @ We1_e (single K=32 chunk) ========
    CP_WAIT0();
    __syncthreads();
    compute((const uint32_t*)sm, 32, 0, (const uint32_t*)(sm + 65536));
    __syncthreads();

    // epilogue A: write raw T into Ys, zero accumulators
#pragma unroll
    for (int mf = 0; mf < 2; mf++) {
        int r0r = m0 + mf * 16 + g;
#pragma unroll
        for (int nf = 0; nf < 8; nf++) {
            int cc = n0 + 8 * nf + 2 * t4;
            int w = (cc & ~31) + ((cc & 31) ^ (4 * g));
            *(float2*)&Ys[r0r * 128 + w]       = make_float2(c[mf][nf][0], c[mf][nf][1]);
            *(float2*)&Ys[(r0r + 8) * 128 + w] = make_float2(c[mf][nf][2], c[mf][nf][3]);
#pragma unroll
            for (int j = 0; j < 4; j++) c[mf][nf][j] = 0.0f;
        }
    }
    // prefetch W2 chunk 0 (overlaps P-merge)
    issue_w(g_W2r, 0, 0); CP_COMMIT();
    __syncthreads();

    // ---- P-merge: Y = relu(T + P[src].lo + P[dst].hi + b1) ----
#pragma unroll 4
    for (int i = 0; i < 16; i++) {
        int f = tid + i * 256;
        int row = f >> 5, c4 = f & 31;
        int w = row * 128 + (c4 >> 3) * 32 + ((4 * (c4 & 7)) ^ (4 * (row & 7)));
        float4 t = *(const float4*)&Ys[w];
        float4 ps = *(const float4*)(g_P + (size_t)sSrc[row] * 256 + 4 * c4);
        float4 pd = *(const float4*)(g_P + (size_t)sDst[row] * 256 + 128 + 4 * c4);
        float4 b = *(const float4*)&sb1[4 * c4];
        float4 y;
        y.x = fmaxf(t.x + ps.x + pd.x + b.x, 0.0f);
        y.y = fmaxf(t.y + ps.y + pd.y + b.y, 0.0f);
        y.z = fmaxf(t.z + ps.z + pd.z + b.z, 0.0f);
        y.w = fmaxf(t.w + ps.w + pd.w + b.w, 0.0f);
        *(float4*)&Ys[w] = y;
    }

    // ======== phase 2: layer 2, K = 128 = 4 chunks of 32 (A from Ys) ========
    for (int ch = 0; ch < 4; ch++) {
        if (ch < 3) {
            issue_w(g_W2r, ch + 1, (ch + 1) & 1);
            CP_COMMIT(); CP_WAIT1();
        } else CP_WAIT0();
        __syncthreads();
        compute((const uint32_t*)sm, 128, ch * 32,
                (const uint32_t*)(sm + 65536) + (ch & 1) * 4096);
        __syncthreads();
    }

    // ---- stage messages (+bias b2) into Ys ----
#pragma unroll
    for (int mf = 0; mf < 2; mf++) {
        int r0r = m0 + mf * 16 + g;
#pragma unroll
        for (int nf = 0; nf < 8; nf++) {
            int cc = n0 + 8 * nf + 2 * t4;
            float bb0 = sb2[cc], bb1 = sb2[cc + 1];
            int w = (cc & ~31) + ((cc & 31) ^ (4 * g));
            *(float2*)&Ys[r0r * 128 + w] =
                make_float2(c[mf][nf][0] + bb0, c[mf][nf][1] + bb1);
            *(float2*)&Ys[(r0r + 8) * 128 + w] =
                make_float2(c[mf][nf][2] + bb0, c[mf][nf][3] + bb1);
        }
    }
    __syncthreads();

    // ---- coalesced vectorized scatter-add ----
#pragma unroll 4
    for (int i = 0; i < 16; i++) {
        int f = tid + i * 256;
        int row = f >> 5, c4 = f & 31;
        int w = row * 128 + (c4 >> 3) * 32 + ((4 * (c4 & 7)) ^ (4 * (row & 7)));
        float4 v = *(const float4*)&Ys[w];
        float* gp = g_mi + (size_t)sDst[row] * HID + 4 * c4;
        asm volatile("red.global.add.v4.f32 [%0], {%1,%2,%3,%4};"
                     :: "l"(gp), "f"(v.x), "f"(v.y), "f"(v.z), "f"(v.w) : "memory");
    }
}

// =================================================================
// Node MLP kernel (fp32 FFMA2, unchanged — exact math on m_i)
// =================================================================
__global__ __launch_bounds__(256) void node_kernel(
    const float* __restrict__ h,
    const float* __restrict__ W1, const float* __restrict__ b1,
    const float* __restrict__ W2, const float* __restrict__ b2,
    float* __restrict__ out)
{
    __shared__ float Xs[64][17];
    __shared__ float Ws[16][128];
    __shared__ float Ys2[64][129];

    const int t  = threadIdx.x;
    const int r0 = blockIdx.x * 64;
    const int tx = t & 15, ty = t >> 4;
    const int eb = ty * 4, cb = tx * 8;

    u64 acc[4][4];
#pragma unroll
    for (int j = 0; j < 4; j++) {
        u64 bj = pk2(b1[cb + 2 * j], b1[cb + 2 * j + 1]);
        acc[0][j] = bj; acc[1][j] = bj; acc[2][j] = bj; acc[3][j] = bj;
    }

    const int le = t >> 2, lj = t & 3;
    const int lr = (r0 + le < N_NODES) ? (r0 + le) : 0;

    for (int ch = 0; ch < 16; ch++) {
        const float* p;
        if (ch < 8) p = h    + (size_t)lr * DNODE + ch * 16;
        else        p = g_mi + (size_t)lr * HID   + (ch - 8) * 16;
        float4 v = *(const float4*)(p + lj * 4);

        const float* wsrc = W1 + (size_t)ch * 16 * 128;
#pragma unroll
        for (int r2 = 0; r2 < 2; r2++) {
            int f = t + r2 * 256;
            int rw = f >> 5, c = (f & 31) * 4;
            *(float4*)&Ws[rw][c] = *(const float4*)(wsrc + rw * 128 + c);
        }
        Xs[le][lj * 4 + 0] = v.x; Xs[le][lj * 4 + 1] = v.y;
        Xs[le][lj * 4 + 2] = v.z; Xs[le][lj * 4 + 3] = v.w;
        __syncthreads();

#pragma unroll
        for (int kk = 0; kk < 16; kk++) {
            ulonglong2 w01 = *(const ulonglong2*)&Ws[kk][cb];
            ulonglong2 w23 = *(const ulonglong2*)&Ws[kk][cb + 4];
            float a0 = Xs[eb + 0][kk], a1 = Xs[eb + 1][kk];
            float a2 = Xs[eb + 2][kk], a3 = Xs[eb + 3][kk];
            u64 A0 = pk2(a0, a0), A1 = pk2(a1, a1), A2 = pk2(a2, a2), A3 = pk2(a3, a3);
            fma2(acc[0][0], A0, w01.x); fma2(acc[0][1], A0, w01.y);
            fma2(acc[0][2], A0, w23.x); fma2(acc[0][3], A0, w23.y);
            fma2(acc[1][0], A1, w01.x); fma2(acc[1][1], A1, w01.y);
            fma2(acc[1][2], A1, w23.x); fma2(acc[1][3], A1, w23.y);
            fma2(acc[2][0], A2, w01.x); fma2(acc[2][1], A2, w01.y);
            fma2(acc[2][2], A2, w23.x); fma2(acc[2][3], A2, w23.y);
            fma2(acc[3][0], A3, w01.x); fma2(acc[3][1], A3, w01.y);
            fma2(acc[3][2], A3, w23.x); fma2(acc[3][3], A3, w23.y);
        }
        __syncthreads();
    }

#pragma unroll
    for (int i = 0; i < 4; i++)
#pragma unroll
        for (int j = 0; j < 4; j++) {
            float2 v = upk2(acc[i][j]);
            Ys2[eb + i][cb + 2 * j]     = fmaxf(v.x, 0.0f);
            Ys2[eb + i][cb + 2 * j + 1] = fmaxf(v.y, 0.0f);
        }
#pragma unroll
    for (int j = 0; j < 4; j++) {
        u64 bj = pk2(b2[cb + 2 * j], b2[cb + 2 * j + 1]);
        acc[0][j] = bj; acc[1][j] = bj; acc[2][j] = bj; acc[3][j] = bj;
    }
    __syncthreads();

    for (int ch = 0; ch < 8; ch++) {
        const float* wsrc = W2 + (size_t)ch * 16 * 128;
#pragma unroll
        for (int r2 = 0; r2 < 2; r2++) {
            int f = t + r2 * 256;
            int rw = f >> 5, c = (f & 31) * 4;
            *(float4*)&Ws[rw][c] = *(const float4*)(wsrc + rw * 128 + c);
        }
        __syncthreads();
#pragma unroll
        for (int kk = 0; kk < 16; kk++) {
            int k = ch * 16 + kk;
            ulonglong2 w01 = *(const ulonglong2*)&Ws[kk][cb];
            ulonglong2 w23 = *(const ulonglong2*)&Ws[kk][cb + 4];
            float a0 = Ys2[eb + 0][k], a1 = Ys2[eb + 1][k];
            float a2 = Ys2[eb + 2][k], a3 = Ys2[eb + 3][k];
            u64 A0 = pk2(a0, a0), A1 = pk2(a1, a1), A2 = pk2(a2, a2), A3 = pk2(a3, a3);
            fma2(acc[0][0], A0, w01.x); fma2(acc[0][1], A0, w01.y);
            fma2(acc[0][2], A0, w23.x); fma2(acc[0][3], A0, w23.y);
            fma2(acc[1][0], A1, w01.x); fma2(acc[1][1], A1, w01.y);
            fma2(acc[1][2], A1, w23.x); fma2(acc[1][3], A1, w23.y);
            fma2(acc[2][0], A2, w01.x); fma2(acc[2][1], A2, w01.y);
            fma2(acc[2][2], A2, w23.x); fma2(acc[2][3], A2, w23.y);
            fma2(acc[3][0], A3, w01.x); fma2(acc[3][1], A3, w01.y);
            fma2(acc[3][2], A3, w23.x); fma2(acc[3][3], A3, w23.y);
        }
        __syncthreads();
    }

#pragma unroll
    for (int i = 0; i < 4; i++) {
        int rw = r0 + eb + i;
        if (rw < N_NODES) {
            float* op = out + (size_t)rw * 128 + cb;
#pragma unroll
            for (int j = 0; j < 4; j++) {
                float2 v = upk2(acc[i][j]);
                op[2 * j]     = v.x;
                op[2 * j + 1] = v.y;
            }
        }
    }
}

// =================================================================
extern "C" void kernel_launch(void* const* d_in, const int* in_sizes, int n_in,
                              void* d_out, int out_size) {
    const float* h   = (const float*)d_in[0];
    const void*  ei  = d_in[1];
    const float* ea  = (const float*)d_in[2];
    const float* We1 = (const float*)d_in[3];
    const float* be1 = (const float*)d_in[4];
    const float* We2 = (const float*)d_in[5];
    const float* be2 = (const float*)d_in[6];
    const float* Wh1 = (const float*)d_in[7];
    const float* bh1 = (const float*)d_in[8];
    const float* Wh2 = (const float*)d_in[9];
    const float* bh2 = (const float*)d_in[10];
    float* out = (float*)d_out;

    cudaFuncSetAttribute(edge_kernel_m, cudaFuncAttributeMaxDynamicSharedMemorySize, EDGE_SMEM);
    cudaFuncSetAttribute(gemm_P, cudaFuncAttributeMaxDynamicSharedMemorySize, GP_SMEM);

    detect_kernel<<<1, 32>>>((const int*)ei);
    convert_kernel<<<(N_EDGES + 255) / 256, 256>>>(ei);
    zero_kernel<<<2048, 256>>>();
    prep_kernel<<<64, 256>>>(We1, We2);
    gemm_P<<<(N_NODES + 127) / 128, 256, GP_SMEM>>>(h);
    edge_kernel_m<<<N_EDGES / 128, 256, EDGE_SMEM>>>(ea, be1, be2);
    node_kernel<<<(N_NODES + 63) / 64, 256>>>(h, Wh1, bh1, Wh2, bh2, out);
}

// round 6
// speedup vs baseline: 6.5935x; 1.2527x over previous
#include <cuda_runtime.h>
#include <cstdint>

#define N_NODES 50000
#define N_EDGES 800000
#define DNODE   128
#define DEDGE   32
#define HID     128

typedef unsigned long long u64;

// ---------------- device-global scratch (no allocations allowed) ----------------
__device__ int   g_src[N_EDGES];
__device__ int   g_dst[N_EDGES];
__device__ float g_mi[(size_t)N_NODES * HID];      // 25.6 MB scatter target
__device__ float g_P[(size_t)N_NODES * 256];       // 51.2 MB: [h@W1a | h@W1b]
__device__ float g_W1r[288 * 128];                 // We1, tf32-rounded (RNA), [K][N]
__device__ float g_W2r[128 * 128];                 // We2, tf32-rounded (RNA), [K][N]
__device__ float g_Wh1hi[256 * 128];               // Wh1 split hi/lo (3xTF32)
__device__ float g_Wh1lo[256 * 128];
__device__ float g_Wh2hi[128 * 128];
__device__ float g_Wh2lo[128 * 128];

// ---------------- helpers ----------------
__device__ __forceinline__ uint32_t smem_u32(const void* p) {
    uint32_t a;
    asm("{ .reg .u64 t; cvta.to.shared.u64 t, %1; cvt.u32.u64 %0, t; }" : "=r"(a) : "l"(p));
    return a;
}
__device__ __forceinline__ uint32_t rna(float x) {
    uint32_t r; asm("cvt.rna.tf32.f32 %0, %1;" : "=r"(r) : "f"(x)); return r;
}

#define CP_ASYNC(ds, gp) \
    asm volatile("cp.async.cg.shared.global [%0], [%1], 16;" :: "r"(ds), "l"(gp))
#define CP_COMMIT() asm volatile("cp.async.commit_group;" ::: "memory")
#define CP_WAIT1()  asm volatile("cp.async.wait_group 1;" ::: "memory")
#define CP_WAIT0()  asm volatile("cp.async.wait_group 0;" ::: "memory")

#define MMA_TF32(C, a0, a1, a2, a3, b0, b1) \
    asm volatile("mma.sync.aligned.m16n8k8.row.col.f32.tf32.tf32.f32 " \
        "{%0,%1,%2,%3}, {%4,%5,%6,%7}, {%8,%9}, {%0,%1,%2,%3};" \
        : "+f"((C)[0]), "+f"((C)[1]), "+f"((C)[2]), "+f"((C)[3]) \
        : "r"(a0), "r"(a1), "r"(a2), "r"(a3), "r"(b0), "r"(b1))

// ---------------- aux kernel: dtype-detect + index convert + zero g_mi ----------------
__global__ void convert_kernel(const void* __restrict__ ei) {
    __shared__ int s64;
    if (threadIdx.x == 0) {
        const int* p = (const int*)ei;
        int all0 = 1;
        for (int s = 0; s < 256; s++)
            if (p[2 * s + 1] != 0) { all0 = 0; break; }
        s64 = all0;
    }
    __syncthreads();
    int i = blockIdx.x * blockDim.x + threadIdx.x;
    if (i < N_EDGES) {
        if (s64) {
            const long long* p = (const long long*)ei;
            g_src[i] = (int)p[i];
            g_dst[i] = (int)p[N_EDGES + i];
        } else {
            const int* p = (const int*)ei;
            g_src[i] = p[i];
            g_dst[i] = p[N_EDGES + i];
        }
    }
    // zero g_mi (6.4M floats) with float4 stores
    size_t n4 = (size_t)N_NODES * HID / 4;
    float4 z = make_float4(0.f, 0.f, 0.f, 0.f);
    for (size_t j = (size_t)blockIdx.x * blockDim.x + threadIdx.x; j < n4;
         j += (size_t)gridDim.x * blockDim.x)
        ((float4*)g_mi)[j] = z;
}

// ---------------- prep: RNA-round edge weights, split node weights hi/lo ----------------
__global__ void prep_kernel(const float* __restrict__ W1, const float* __restrict__ W2,
                            const float* __restrict__ Wh1, const float* __restrict__ Wh2) {
    int t = blockIdx.x * blockDim.x + threadIdx.x;
    int stride = gridDim.x * blockDim.x;
    for (int i = t; i < 288 * 128; i += stride)
        g_W1r[i] = __uint_as_float(rna(W1[i]));
    for (int i = t; i < 128 * 128; i += stride)
        g_W2r[i] = __uint_as_float(rna(W2[i]));
    for (int i = t; i < 256 * 128; i += stride) {
        float w = Wh1[i];
        uint32_t hi = rna(w);
        g_Wh1hi[i] = __uint_as_float(hi);
        g_Wh1lo[i] = __uint_as_float(rna(w - __uint_as_float(hi)));
    }
    for (int i = t; i < 128 * 128; i += stride) {
        float w = Wh2[i];
        uint32_t hi = rna(w);
        g_Wh2hi[i] = __uint_as_float(hi);
        g_Wh2lo[i] = __uint_as_float(rna(w - __uint_as_float(hi)));
    }
}

// =================================================================
// Precompute P = h @ [We1_a | We1_b]  (50k x 128 x 256, tf32 mma)
// Block: 128 rows x 256 cols, 8 warps (2m x 4n), warp tile 64x64.
// =================================================================
#define GP_SMEM 98304

__global__ __launch_bounds__(256) void gemm_P(const float* __restrict__ h) {
    extern __shared__ char sm[];
    const uint32_t smb = smem_u32(sm);
    const int tid = threadIdx.x, lane = tid & 31, wid = tid >> 5;
    const int g = lane >> 2, t4 = lane & 3;
    const int m0 = (wid >> 2) * 64, n0 = (wid & 3) * 64;
    const int r0 = blockIdx.x * 128;

    auto issue_x = [&](int ch, int b) {
        uint32_t xb = smb + b * 16384;
#pragma unroll
        for (int i = 0; i < 4; i++) {
            int f = tid + i * 256;
            int row = f >> 3, q = f & 7;
            int gr = r0 + row; if (gr >= N_NODES) gr = 0;
            const float* gp = h + (size_t)gr * DNODE + ch * 32 + q * 4;
            uint32_t ds = xb + 4u * (uint32_t)(row * 32 + ((4 * q) ^ (4 * (row & 7))));
            CP_ASYNC(ds, gp);
        }
    };
    auto issue_w = [&](int ch, int b) {
        uint32_t wb = smb + 32768 + b * 32768;
#pragma unroll
        for (int i = 0; i < 8; i++) {
            int f = tid + i * 256;
            int k = f >> 6, n4 = f & 63;
            int n = 4 * n4;
            const float* gp = (n < 128)
                ? g_W1r + (size_t)(ch * 32 + k) * 128 + n
                : g_W1r + (size_t)(128 + ch * 32 + k) * 128 + (n - 128);
            uint32_t ds = wb + 4u * (uint32_t)(k * 256 + (n ^ (8 * (k & 3))));
            CP_ASYNC(ds, gp);
        }
    };

    float c[4][8][4];
#pragma unroll
    for (int mf = 0; mf < 4; mf++)
#pragma unroll
        for (int nf = 0; nf < 8; nf++)
#pragma unroll
            for (int j = 0; j < 4; j++) c[mf][nf][j] = 0.0f;

    issue_x(0, 0); issue_w(0, 0); CP_COMMIT();
    for (int ch = 0; ch < 4; ch++) {
        if (ch < 3) {
            issue_x(ch + 1, (ch + 1) & 1);
            issue_w(ch + 1, (ch + 1) & 1);
            CP_COMMIT(); CP_WAIT1();
        } else CP_WAIT0();
        __syncthreads();
        const uint32_t* Xw = (const uint32_t*)sm + (ch & 1) * 4096;
        const uint32_t* Ww = (const uint32_t*)(sm + 32768) + (ch & 1) * 8192;
#pragma unroll
        for (int s = 0; s < 4; s++) {
            const int kb = 8 * s + t4;
            uint32_t b0r[8], b1r[8];
#pragma unroll
            for (int nf = 0; nf < 8; nf++) {
                int wc = (n0 + 8 * nf + g) ^ (8 * t4);
                b0r[nf] = Ww[kb * 256 + wc];
                b1r[nf] = Ww[(kb + 4) * 256 + wc];
            }
#pragma unroll
            for (int mf = 0; mf < 4; mf++) {
                int base = (m0 + mf * 16 + g) * 32;
                uint32_t a0 = Xw[base + (kb ^ (4 * g))];
                uint32_t a1 = Xw[base + 8 * 32 + (kb ^ (4 * g))];
                uint32_t a2 = Xw[base + ((kb + 4) ^ (4 * g))];
                uint32_t a3 = Xw[base + 8 * 32 + ((kb + 4) ^ (4 * g))];
#pragma unroll
                for (int nf = 0; nf < 8; nf++)
                    MMA_TF32(c[mf][nf], a0, a1, a2, a3, b0r[nf], b1r[nf]);
            }
        }
        __syncthreads();
    }

#pragma unroll
    for (int mf = 0; mf < 4; mf++) {
        int r = m0 + mf * 16 + g;
#pragma unroll
        for (int nf = 0; nf < 8; nf++) {
            int col = n0 + 8 * nf + 2 * t4;
            if (r0 + r < N_NODES)
                *(float2*)(g_P + (size_t)(r0 + r) * 256 + col) =
                    make_float2(c[mf][nf][0], c[mf][nf][1]);
            if (r0 + r + 8 < N_NODES)
                *(float2*)(g_P + (size_t)(r0 + r + 8) * 256 + col) =
                    make_float2(c[mf][nf][2], c[mf][nf][3]);
        }
    }
}

// =================================================================
// Edge kernel: 128 edges/block, 2 CTAs/SM (unchanged from R5).
// =================================================================
#define EDGE_SMEM 100352

__global__ __launch_bounds__(256, 2) void edge_kernel_m(
    const float* __restrict__ ea,
    const float* __restrict__ b1g, const float* __restrict__ b2g)
{
    extern __shared__ char sm[];
    const uint32_t smb = smem_u32(sm);
    float* Ys  = (float*)sm;
    float* sb1 = (float*)(sm + 98304);
    float* sb2 = (float*)(sm + 98816);
    int*   sSrc = (int*)(sm + 99328);
    int*   sDst = (int*)(sm + 99840);

    const int tid  = threadIdx.x;
    const int lane = tid & 31, wid = tid >> 5;
    const int g    = lane >> 2, t4 = lane & 3;
    const int m0   = (wid >> 1) * 32;
    const int n0   = (wid & 1) * 64;
    const int e0   = blockIdx.x * 128;

    if (tid < 128) {
        sb1[tid] = b1g[tid];
        sb2[tid] = b2g[tid];
        sSrc[tid] = g_src[e0 + tid];
        sDst[tid] = g_dst[e0 + tid];
    }

#pragma unroll
    for (int i = 0; i < 4; i++) {
        int f = tid + i * 256;
        int row = f >> 3, q = f & 7;
        const float* gp = ea + (size_t)(e0 + row) * DEDGE + q * 4;
        uint32_t ds = smb + 4u * (uint32_t)(row * 32 + ((4 * q) ^ (4 * (row & 7))));
        CP_ASYNC(ds, gp);
    }
    auto issue_w = [&](const float* W, int ch, int wb) {
        uint32_t wbase = smb + 65536 + wb * 16384;
#pragma unroll
        for (int i = 0; i < 4; i++) {
            int f = tid + i * 256;
            int k = f >> 5, n4 = f & 31;
            const float* gp = W + (size_t)(ch * 32 + k) * 128 + n4 * 4;
            uint32_t ds = wbase + 4u * (uint32_t)(k * 128 + ((4 * n4) ^ (8 * (k & 3))));
            CP_ASYNC(ds, gp);
        }
    };
    issue_w(g_W1r, 8, 0);
    CP_COMMIT();

    float c[2][8][4];
#pragma unroll
    for (int mf = 0; mf < 2; mf++)
#pragma unroll
        for (int nf = 0; nf < 8; nf++)
#pragma unroll
            for (int j = 0; j < 4; j++) c[mf][nf][j] = 0.0f;

    auto compute = [&](const uint32_t* Xw, int rstride, int cofs, const uint32_t* Ww) {
#pragma unroll
        for (int s = 0; s < 4; s++) {
            const int kb = 8 * s + t4;
            uint32_t b0r[8], b1r[8];
#pragma unroll
            for (int nf = 0; nf < 8; nf++) {
                int wc = (n0 + 8 * nf + g) ^ (8 * t4);
                b0r[nf] = Ww[kb * 128 + wc];
                b1r[nf] = Ww[(kb + 4) * 128 + wc];
            }
#pragma unroll
            for (int mf = 0; mf < 2; mf++) {
                int base = (m0 + mf * 16 + g) * rstride + cofs;
                uint32_t a0 = Xw[base + (kb ^ (4 * g))];
                uint32_t a1 = Xw[base + 8 * rstride + (kb ^ (4 * g))];
                uint32_t a2 = Xw[base + ((kb + 4) ^ (4 * g))];
                uint32_t a3 = Xw[base + 8 * rstride + ((kb + 4) ^ (4 * g))];
#pragma unroll
                for (int nf = 0; nf < 8; nf++)
                    MMA_TF32(c[mf][nf], a0, a1, a2, a3, b0r[nf], b1r[nf]);
            }
        }
    };

    CP_WAIT0();
    __syncthreads();
    compute((const uint32_t*)sm, 32, 0, (const uint32_t*)(sm + 65536));
    __syncthreads();

#pragma unroll
    for (int mf = 0; mf < 2; mf++) {
        int r0r = m0 + mf * 16 + g;
#pragma unroll
        for (int nf = 0; nf < 8; nf++) {
            int cc = n0 + 8 * nf + 2 * t4;
            int w = (cc & ~31) + ((cc & 31) ^ (4 * g));
            *(float2*)&Ys[r0r * 128 + w]       = make_float2(c[mf][nf][0], c[mf][nf][1]);
            *(float2*)&Ys[(r0r + 8) * 128 + w] = make_float2(c[mf][nf][2], c[mf][nf][3]);
#pragma unroll
            for (int j = 0; j < 4; j++) c[mf][nf][j] = 0.0f;
        }
    }
    issue_w(g_W2r, 0, 0); CP_COMMIT();
    __syncthreads();

#pragma unroll 4
    for (int i = 0; i < 16; i++) {
        int f = tid + i * 256;
        int row = f >> 5, c4 = f & 31;
        int w = row * 128 + (c4 >> 3) * 32 + ((4 * (c4 & 7)) ^ (4 * (row & 7)));
        float4 t = *(const float4*)&Ys[w];
        float4 ps = *(const float4*)(g_P + (size_t)sSrc[row] * 256 + 4 * c4);
        float4 pd = *(const float4*)(g_P + (size_t)sDst[row] * 256 + 128 + 4 * c4);
        float4 b = *(const float4*)&sb1[4 * c4];
        float4 y;
        y.x = fmaxf(t.x + ps.x + pd.x + b.x, 0.0f);
        y.y = fmaxf(t.y + ps.y + pd.y + b.y, 0.0f);
        y.z = fmaxf(t.z + ps.z + pd.z + b.z, 0.0f);
        y.w = fmaxf(t.w + ps.w + pd.w + b.w, 0.0f);
        *(float4*)&Ys[w] = y;
    }

    for (int ch = 0; ch < 4; ch++) {
        if (ch < 3) {
            issue_w(g_W2r, ch + 1, (ch + 1) & 1);
            CP_COMMIT(); CP_WAIT1();
        } else CP_WAIT0();
        __syncthreads();
        compute((const uint32_t*)sm, 128, ch * 32,
                (const uint32_t*)(sm + 65536) + (ch & 1) * 4096);
        __syncthreads();
    }

#pragma unroll
    for (int mf = 0; mf < 2; mf++) {
        int r0r = m0 + mf * 16 + g;
#pragma unroll
        for (int nf = 0; nf < 8; nf++) {
            int cc = n0 + 8 * nf + 2 * t4;
            float bb0 = sb2[cc], bb1 = sb2[cc + 1];
            int w = (cc & ~31) + ((cc & 31) ^ (4 * g));
            *(float2*)&Ys[r0r * 128 + w] =
                make_float2(c[mf][nf][0] + bb0, c[mf][nf][1] + bb1);
            *(float2*)&Ys[(r0r + 8) * 128 + w] =
                make_float2(c[mf][nf][2] + bb0, c[mf][nf][3] + bb1);
        }
    }
    __syncthreads();

#pragma unroll 4
    for (int i = 0; i < 16; i++) {
        int f = tid + i * 256;
        int row = f >> 5, c4 = f & 31;
        int w = row * 128 + (c4 >> 3) * 32 + ((4 * (c4 & 7)) ^ (4 * (row & 7)));
        float4 v = *(const float4*)&Ys[w];
        float* gp = g_mi + (size_t)sDst[row] * HID + 4 * c4;
        asm volatile("red.global.add.v4.f32 [%0], {%1,%2,%3,%4};"
                     :: "l"(gp), "f"(v.x), "f"(v.y), "f"(v.z), "f"(v.w) : "memory");
    }
}

// =================================================================
// Node MLP via 3xTF32 split mma (error ~2^-21, preserves fp32 accuracy).
// Block = 64 nodes, 8 warps (4m x 2n), warp tile 16x64. c[8][4].
// smem map (bytes):
//   [0, 32768)       Ys: 64 rows x 128 words (X chunk double-buffer overlays
//                     [0,16384): each 64 rows x 32 words = 8 KB)
//   [32768, 98304)   W stage b in {0,1}: hi @ 32768+b*32768, lo @ +16384
//   [98304, 98816)   sb1   [98816, 99328)  sb2
// =================================================================
#define NODE_SMEM 99328

__global__ __launch_bounds__(256, 2) void node_kernel_m(
    const float* __restrict__ h,
    const float* __restrict__ b1g, const float* __restrict__ b2g,
    float* __restrict__ out)
{
    extern __shared__ char sm[];
    const uint32_t smb = smem_u32(sm);
    float* Ys  = (float*)sm;
    float* sb1 = (float*)(sm + 98304);
    float* sb2 = (float*)(sm + 98816);

    const int tid  = threadIdx.x;
    const int lane = tid & 31, wid = tid >> 5;
    const int g    = lane >> 2, t4 = lane & 3;
    const int m0   = (wid >> 1) * 16;    // 4 m-warps x 16 rows
    const int n0   = (wid & 1) * 64;     // 2 n-warps x 64 cols
    const int r0   = blockIdx.x * 64;

    if (tid < 128) { sb1[tid] = b1g[tid]; sb2[tid] = b2g[tid]; }

    // X chunk loader: 64 rows x 32 floats (8 KB); layer1 K=256: ch<4 from h, else g_mi
    auto issue_x = [&](int ch, int b) {
        uint32_t xb = smb + b * 8192;
#pragma unroll
        for (int i = 0; i < 2; i++) {
            int f = tid + i * 256;
            int row = f >> 3, q = f & 7;
            int gr = r0 + row; if (gr >= N_NODES) gr = 0;
            const float* gp = (ch < 4)
                ? h    + (size_t)gr * DNODE + ch * 32 + q * 4
                : g_mi + (size_t)gr * HID   + (ch - 4) * 32 + q * 4;
            uint32_t ds = xb + 4u * (uint32_t)(row * 32 + ((4 * q) ^ (4 * (row & 7))));
            CP_ASYNC(ds, gp);
        }
    };
    // W chunk loader: 32k x 128n, hi+lo (16 KB each)
    auto issue_w = [&](const float* Whi, const float* Wlo, int ch, int b) {
        uint32_t base_hi = smb + 32768 + b * 32768;
#pragma unroll
        for (int i = 0; i < 4; i++) {
            int f = tid + i * 256;
            int k = f >> 5, n4 = f & 31;
            uint32_t off = 4u * (uint32_t)(k * 128 + ((4 * n4) ^ (8 * (k & 3))));
            CP_ASYNC(base_hi + off,         Whi + (size_t)(ch * 32 + k) * 128 + n4 * 4);
            CP_ASYNC(base_hi + 16384 + off, Wlo + (size_t)(ch * 32 + k) * 128 + n4 * 4);
        }
    };

    float c[8][4];
#pragma unroll
    for (int nf = 0; nf < 8; nf++)
#pragma unroll
        for (int j = 0; j < 4; j++) c[nf][j] = 0.0f;

    // 3xTF32 compute of one K=32 chunk
    auto computeN = [&](const uint32_t* Xw, int rstride, int cofs,
                        const uint32_t* Whi, const uint32_t* Wlo) {
#pragma unroll
        for (int s = 0; s < 4; s++) {
            const int kb = 8 * s + t4;
            int base0 = (m0 + g) * rstride + cofs;
            int base1 = (m0 + 8 + g) * rstride + cofs;
            float x0 = __uint_as_float(Xw[base0 + (kb ^ (4 * g))]);
            float x1 = __uint_as_float(Xw[base1 + (kb ^ (4 * g))]);
            float x2 = __uint_as_float(Xw[base0 + ((kb + 4) ^ (4 * g))]);
            float x3 = __uint_as_float(Xw[base1 + ((kb + 4) ^ (4 * g))]);
            uint32_t h0 = rna(x0), h1 = rna(x1), h2 = rna(x2), h3 = rna(x3);
            uint32_t l0 = rna(x0 - __uint_as_float(h0));
            uint32_t l1 = rna(x1 - __uint_as_float(h1));
            uint32_t l2 = rna(x2 - __uint_as_float(h2));
            uint32_t l3 = rna(x3 - __uint_as_float(h3));
#pragma unroll
            for (int nf = 0; nf < 8; nf++) {
                int wc = (n0 + 8 * nf + g) ^ (8 * t4);
                uint32_t bh0 = Whi[kb * 128 + wc], bh1 = Whi[(kb + 4) * 128 + wc];
                uint32_t bl0 = Wlo[kb * 128 + wc], bl1 = Wlo[(kb + 4) * 128 + wc];
                MMA_TF32(c[nf], h0, h1, h2, h3, bh0, bh1);
                MMA_TF32(c[nf], l0, l1, l2, l3, bh0, bh1);
                MMA_TF32(c[nf], h0, h1, h2, h3, bl0, bl1);
            }
        }
    };

    // ======== layer 1: K = 256 = 8 chunks of 32 ========
    issue_x(0, 0); issue_w(g_Wh1hi, g_Wh1lo, 0, 0); CP_COMMIT();
    for (int ch = 0; ch < 8; ch++) {
        if (ch < 7) {
            issue_x(ch + 1, (ch + 1) & 1);
            issue_w(g_Wh1hi, g_Wh1lo, ch + 1, (ch + 1) & 1);
            CP_COMMIT(); CP_WAIT1();
        } else CP_WAIT0();
        __syncthreads();
        computeN((const uint32_t*)sm + (ch & 1) * 2048, 32, 0,
                 (const uint32_t*)(sm + 32768 + (ch & 1) * 32768),
                 (const uint32_t*)(sm + 32768 + (ch & 1) * 32768 + 16384));
        __syncthreads();
    }

    // ---- epilogue 1: relu(x + b1) -> Ys (swizzled), zero c ----
#pragma unroll
    for (int nf = 0; nf < 8; nf++) {
        int cc = n0 + 8 * nf + 2 * t4;
        float bb0 = sb1[cc], bb1 = sb1[cc + 1];
        int w = (cc & ~31) + ((cc & 31) ^ (4 * g));
        *(float2*)&Ys[(m0 + g) * 128 + w] =
            make_float2(fmaxf(c[nf][0] + bb0, 0.0f), fmaxf(c[nf][1] + bb1, 0.0f));
        *(float2*)&Ys[(m0 + 8 + g) * 128 + w] =
            make_float2(fmaxf(c[nf][2] + bb0, 0.0f), fmaxf(c[nf][3] + bb1, 0.0f));
#pragma unroll
        for (int j = 0; j < 4; j++) c[nf][j] = 0.0f;
    }
    issue_w(g_Wh2hi, g_Wh2lo, 0, 0); CP_COMMIT();
    __syncthreads();

    // ======== layer 2: K = 128 = 4 chunks of 32 (A from Ys) ========
    for (int ch = 0; ch < 4; ch++) {
        if (ch < 3) {
            issue_w(g_Wh2hi, g_Wh2lo, ch + 1, (ch + 1) & 1);
            CP_COMMIT(); CP_WAIT1();
        } else CP_WAIT0();
        __syncthreads();
        computeN((const uint32_t*)sm, 128, ch * 32,
                 (const uint32_t*)(sm + 32768 + (ch & 1) * 32768),
                 (const uint32_t*)(sm + 32768 + (ch & 1) * 32768 + 16384));
        __syncthreads();
    }

    // ---- store out = c + b2 ----
#pragma unroll
    for (int nf = 0; nf < 8; nf++) {
        int cc = n0 + 8 * nf + 2 * t4;
        float bb0 = sb2[cc], bb1 = sb2[cc + 1];
        int ra = r0 + m0 + g, rb = ra + 8;
        if (ra < N_NODES)
            *(float2*)(out + (size_t)ra * 128 + cc) =
                make_float2(c[nf][0] + bb0, c[nf][1] + bb1);
        if (rb < N_NODES)
            *(float2*)(out + (size_t)rb * 128 + cc) =
                make_float2(c[nf][2] + bb0, c[nf][3] + bb1);
    }
}

// =================================================================
extern "C" void kernel_launch(void* const* d_in, const int* in_sizes, int n_in,
                              void* d_out, int out_size) {
    const float* h   = (const float*)d_in[0];
    const void*  ei  = d_in[1];
    const float* ea  = (const float*)d_in[2];
    const float* We1 = (const float*)d_in[3];
    const float* be1 = (const float*)d_in[4];
    const float* We2 = (const float*)d_in[5];
    const float* be2 = (const float*)d_in[6];
    const float* Wh1 = (const float*)d_in[7];
    const float* bh1 = (const float*)d_in[8];
    const float* Wh2 = (const float*)d_in[9];
    const float* bh2 = (const float*)d_in[10];
    float* out = (float*)d_out;

    cudaFuncSetAttribute(edge_kernel_m, cudaFuncAttributeMaxDynamicSharedMemorySize, EDGE_SMEM);
    cudaFuncSetAttribute(gemm_P, cudaFuncAttributeMaxDynamicSharedMemorySize, GP_SMEM);
    cudaFuncSetAttribute(node_kernel_m, cudaFuncAttributeMaxDynamicSharedMemorySize, NODE_SMEM);

    convert_kernel<<<(N_EDGES + 255) / 256, 256>>>(ei);           // convert + zero
    prep_kernel<<<64, 256>>>(We1, We2, Wh1, Wh2);                 // round + split
    gemm_P<<<(N_NODES + 127) / 128, 256, GP_SMEM>>>(h);
    edge_kernel_m<<<N_EDGES / 128, 256, EDGE_SMEM>>>(ea, be1, be2);
    node_kernel_m<<<(N_NODES + 63) / 64, 256, NODE_SMEM>>>(h, bh1, bh2, out);
}